// round 3
// baseline (speedup 1.0000x reference)
#include <cuda_runtime.h>
#include <math.h>
#include <stdint.h>

// ---------------- problem constants ----------------
#define T_ 1024
#define H_ 1024
#define I_ 512
#define E_ 64
#define S_ 2
#define G_ 8
#define TG_ 4
#define K_ 8
#define NEXP 66                     // 64 routed + 2 shared
#define ROUTED_ENTRIES (T_ * K_)    // 8192
#define ENTRIES (ROUTED_ENTRIES + S_ * T_)  // 10240
#define SLOTS (K_ + S_)             // 10
#define MAXTILES 32                 // ceil(T_/BM), worst case one expert gets all tokens
#define BM 32
#define BK 16

// ---------------- device scratch (static, no allocs) ----------------
__device__ float g_logits[T_ * E_];
__device__ int   g_topk_idx[T_ * K_];
__device__ float g_topk_w[T_ * K_];
__device__ int   g_cnt[NEXP];
__device__ int   g_off[NEXP];
__device__ int   g_fill[E_];
__device__ int   g_etok[ENTRIES];
__device__ int   g_eslot[ENTRIES];
__device__ float g_ew[ENTRIES];
__device__ float g_hidden[(size_t)ENTRIES * I_];        // 21 MB
__device__ float g_contrib[(size_t)T_ * SLOTS * H_];    // 42 MB

// ---------------- packed f32x2 helpers ----------------
typedef unsigned long long u64;

__device__ __forceinline__ u64 pack2(float a, float b) {
    u64 r;
    asm("mov.b64 %0, {%1,%2};" : "=l"(r) : "f"(a), "f"(b));
    return r;
}
__device__ __forceinline__ void fma2(u64& d, u64 a, u64 b) {
    asm("fma.rn.f32x2 %0, %1, %2, %0;" : "+l"(d) : "l"(a), "l"(b));
}
__device__ __forceinline__ float2 unpack2(u64 v) {
    float2 f;
    asm("mov.b64 {%0,%1}, %2;" : "=f"(f.x), "=f"(f.y) : "l"(v));
    return f;
}

// ---------------- kernel 0: zero counters ----------------
__global__ void k_init() {
    int i = threadIdx.x;
    if (i < E_) { g_cnt[i] = 0; g_fill[i] = 0; }
}

// ---------------- kernel 1: gating logits = x @ gate_w^T ----------------
// block: 16 tokens x 64 experts; 256 threads; thread -> 4 tokens, 1 expert
__global__ __launch_bounds__(256) void k_gate(const float* __restrict__ x,
                                              const float* __restrict__ gw) {
    __shared__ float xs[16][64];
    __shared__ float ws[64][65];
    int tid = threadIdx.x;
    int t0 = blockIdx.x * 16;
    int e  = tid & 63;
    int ty = tid >> 6;   // 0..3
    float acc[4] = {0.f, 0.f, 0.f, 0.f};

    for (int k0 = 0; k0 < H_; k0 += 64) {
        #pragma unroll
        for (int j = 0; j < 4; j++) {
            int ii = tid + 256 * j;
            int r = ii >> 6, kk = ii & 63;
            xs[r][kk] = x[(size_t)(t0 + r) * H_ + k0 + kk];
        }
        #pragma unroll
        for (int j = 0; j < 16; j++) {
            int ii = tid + 256 * j;
            int ee = ii >> 6, kk = ii & 63;
            ws[kk][ee] = gw[(size_t)ee * H_ + k0 + kk];
        }
        __syncthreads();
        #pragma unroll 8
        for (int kk = 0; kk < 64; kk++) {
            float b = ws[kk][e];
            #pragma unroll
            for (int m = 0; m < 4; m++) acc[m] += xs[ty + 4 * m][kk] * b;
        }
        __syncthreads();
    }
    #pragma unroll
    for (int m = 0; m < 4; m++)
        g_logits[(size_t)(t0 + ty + 4 * m) * E_ + e] = acc[m];
}

// ---------------- kernel 2: grouped top-k per token ----------------
__global__ void k_topk() {
    int t = blockIdx.x * blockDim.x + threadIdx.x;
    if (t >= T_) return;

    float lv[E_];
    #pragma unroll
    for (int e = 0; e < E_; e++) lv[e] = g_logits[(size_t)t * E_ + e];

    // per-group top-4 (group size = E/G = 8), candidates in (group, rank) order
    float cv[G_ * TG_];
    int   ce[G_ * TG_];   // expert index within group
    #pragma unroll
    for (int g = 0; g < G_; g++) {
        float tmp[8];
        #pragma unroll
        for (int j = 0; j < 8; j++) tmp[j] = lv[g * 8 + j];
        #pragma unroll
        for (int r = 0; r < TG_; r++) {
            int bi = 0; float bv = tmp[0];
            #pragma unroll
            for (int j = 1; j < 8; j++)
                if (tmp[j] > bv) { bv = tmp[j]; bi = j; }
            cv[g * TG_ + r] = bv;
            ce[g * TG_ + r] = bi;
            tmp[bi] = -INFINITY;
        }
    }
    // global top-8 over 32 candidates
    float tw[K_]; int tix[K_];
    float wsum = 0.f;
    #pragma unroll
    for (int r = 0; r < K_; r++) {
        int bi = 0; float bv = cv[0];
        #pragma unroll
        for (int j = 1; j < G_ * TG_; j++)
            if (cv[j] > bv) { bv = cv[j]; bi = j; }
        int grp = bi / TG_;
        tw[r]  = bv;
        tix[r] = grp * 8 + ce[bi];
        cv[bi] = -INFINITY;
        wsum  += bv;
    }
    float inv = 1.0f / (wsum + 1e-20f);
    #pragma unroll
    for (int r = 0; r < K_; r++) {
        g_topk_idx[t * K_ + r] = tix[r];
        g_topk_w[t * K_ + r]   = tw[r] * inv;
        atomicAdd(&g_cnt[tix[r]], 1);
    }
}

// ---------------- kernel 3: offsets (serial scan over 64 counts) ----------------
__global__ void k_off() {
    if (threadIdx.x == 0 && blockIdx.x == 0) {
        int run = 0;
        for (int e = 0; e < E_; e++) { g_off[e] = run; run += g_cnt[e]; }
        g_off[E_]     = ROUTED_ENTRIES;
        g_off[E_ + 1] = ROUTED_ENTRIES + T_;
        g_cnt[E_]     = T_;
        g_cnt[E_ + 1] = T_;
    }
}

// ---------------- kernel 4: scatter entries ----------------
__global__ void k_scatter() {
    int t = blockIdx.x * blockDim.x + threadIdx.x;
    if (t >= T_) return;
    #pragma unroll
    for (int r = 0; r < K_; r++) {
        int e = g_topk_idx[t * K_ + r];
        int p = g_off[e] + atomicAdd(&g_fill[e], 1);
        g_etok[p]  = t;
        g_eslot[p] = r;
        g_ew[p]    = g_topk_w[t * K_ + r];
    }
    #pragma unroll
    for (int s = 0; s < S_; s++) {
        int p = ROUTED_ENTRIES + s * T_ + t;
        g_etok[p]  = t;
        g_eslot[p] = K_ + s;
        g_ew[p]    = 1.0f;
    }
}

// ---------------- kernel 5: gate_up GEMM + fused SiLU ----------------
// grid.x = NEXP*MAXTILES (expert, entry tile of BM), grid.y = I/128 (col tile)
// block 256: thread computes 4 entries x 4 hidden cols, gate+up accumulators.
__global__ __launch_bounds__(256) void k_gateup(const float* __restrict__ x,
                                                const float* __restrict__ w_gu,
                                                const float* __restrict__ s_gu) {
    int e    = blockIdx.x >> 5;    // /MAXTILES
    int tile = blockIdx.x & 31;
    int n = g_cnt[e];
    int r0 = tile * BM;
    if (r0 >= n) return;
    int base = g_off[e];
    int colbase = blockIdx.y * 128;   // within I_
    const float* W = (e < E_) ? (w_gu + (size_t)e * (H_ * 2 * I_))
                              : (s_gu + (size_t)(e - E_) * (H_ * 2 * I_));

    __shared__ __align__(16) float xs[BM][BK];
    __shared__ __align__(16) float wg[BK][128];
    __shared__ __align__(16) float wu[BK][128];

    int tid = threadIdx.x;
    int tx4 = (tid & 31) * 4;   // col within 128-tile
    int ty4 = (tid >> 5) * 4;   // row within BM

    u64 ag[4][2], au[4][2];
    #pragma unroll
    for (int m = 0; m < 4; m++)
        #pragma unroll
        for (int p = 0; p < 2; p++) { ag[m][p] = 0ull; au[m][p] = 0ull; }

    for (int k0 = 0; k0 < H_; k0 += BK) {
        #pragma unroll
        for (int j = 0; j < 2; j++) {
            int i = tid + 256 * j;
            int r = i >> 4, kk = i & 15;
            int rr = r0 + r;
            int tok = (rr < n) ? g_etok[base + rr] : g_etok[base + n - 1];
            xs[r][kk] = x[(size_t)tok * H_ + k0 + kk];
        }
        #pragma unroll
        for (int j = 0; j < 8; j++) {
            int i = tid + 256 * j;
            int kk = i >> 7, c = i & 127;
            size_t rowoff = (size_t)(k0 + kk) * (2 * I_);
            wg[kk][c] = W[rowoff + colbase + c];
            wu[kk][c] = W[rowoff + I_ + colbase + c];
        }
        __syncthreads();
        #pragma unroll
        for (int kk = 0; kk < BK; kk++) {
            float av0 = xs[ty4 + 0][kk];
            float av1 = xs[ty4 + 1][kk];
            float av2 = xs[ty4 + 2][kk];
            float av3 = xs[ty4 + 3][kk];
            u64 a0 = pack2(av0, av0), a1 = pack2(av1, av1);
            u64 a2 = pack2(av2, av2), a3 = pack2(av3, av3);
            ulonglong2 bg = *reinterpret_cast<const ulonglong2*>(&wg[kk][tx4]);
            ulonglong2 bu = *reinterpret_cast<const ulonglong2*>(&wu[kk][tx4]);
            fma2(ag[0][0], a0, bg.x); fma2(ag[0][1], a0, bg.y);
            fma2(ag[1][0], a1, bg.x); fma2(ag[1][1], a1, bg.y);
            fma2(ag[2][0], a2, bg.x); fma2(ag[2][1], a2, bg.y);
            fma2(ag[3][0], a3, bg.x); fma2(ag[3][1], a3, bg.y);
            fma2(au[0][0], a0, bu.x); fma2(au[0][1], a0, bu.y);
            fma2(au[1][0], a1, bu.x); fma2(au[1][1], a1, bu.y);
            fma2(au[2][0], a2, bu.x); fma2(au[2][1], a2, bu.y);
            fma2(au[3][0], a3, bu.x); fma2(au[3][1], a3, bu.y);
        }
        __syncthreads();
    }

    #pragma unroll
    for (int m = 0; m < 4; m++) {
        int rr = r0 + ty4 + m;
        if (rr >= n) continue;
        int ep = base + rr;
        float4 hv;
        float2 g0 = unpack2(ag[m][0]);
        float2 u0 = unpack2(au[m][0]);
        float2 g1 = unpack2(ag[m][1]);
        float2 u1 = unpack2(au[m][1]);
        hv.x = g0.x / (1.0f + expf(-g0.x)) * u0.x;
        hv.y = g0.y / (1.0f + expf(-g0.y)) * u0.y;
        hv.z = g1.x / (1.0f + expf(-g1.x)) * u1.x;
        hv.w = g1.y / (1.0f + expf(-g1.y)) * u1.y;
        *reinterpret_cast<float4*>(g_hidden + (size_t)ep * I_ + colbase + tx4) = hv;
    }
}

// ---------------- kernel 6: down GEMM, weighted, -> contrib[tok][slot][H] ----------------
// grid.x = NEXP*MAXTILES, grid.y = H/128
__global__ __launch_bounds__(256) void k_down(const float* __restrict__ w_d,
                                              const float* __restrict__ s_d) {
    int e    = blockIdx.x >> 5;
    int tile = blockIdx.x & 31;
    int n = g_cnt[e];
    int r0 = tile * BM;
    if (r0 >= n) return;
    int base = g_off[e];
    int colbase = blockIdx.y * 128;   // within H_
    const float* W = (e < E_) ? (w_d + (size_t)e * (I_ * H_))
                              : (s_d + (size_t)(e - E_) * (I_ * H_));

    __shared__ __align__(16) float hs[BM][BK];
    __shared__ __align__(16) float wd[BK][128];

    int tid = threadIdx.x;
    int tx4 = (tid & 31) * 4;
    int ty4 = (tid >> 5) * 4;

    u64 ac[4][2];
    #pragma unroll
    for (int m = 0; m < 4; m++)
        #pragma unroll
        for (int p = 0; p < 2; p++) ac[m][p] = 0ull;

    for (int k0 = 0; k0 < I_; k0 += BK) {
        #pragma unroll
        for (int j = 0; j < 2; j++) {
            int i = tid + 256 * j;
            int r = i >> 4, kk = i & 15;
            int rr = r0 + r;
            int rc = (rr < n) ? rr : (n - 1);
            hs[r][kk] = g_hidden[(size_t)(base + rc) * I_ + k0 + kk];
        }
        #pragma unroll
        for (int j = 0; j < 8; j++) {
            int i = tid + 256 * j;
            int kk = i >> 7, c = i & 127;
            wd[kk][c] = W[(size_t)(k0 + kk) * H_ + colbase + c];
        }
        __syncthreads();
        #pragma unroll
        for (int kk = 0; kk < BK; kk++) {
            float av0 = hs[ty4 + 0][kk];
            float av1 = hs[ty4 + 1][kk];
            float av2 = hs[ty4 + 2][kk];
            float av3 = hs[ty4 + 3][kk];
            u64 a0 = pack2(av0, av0), a1 = pack2(av1, av1);
            u64 a2 = pack2(av2, av2), a3 = pack2(av3, av3);
            ulonglong2 b = *reinterpret_cast<const ulonglong2*>(&wd[kk][tx4]);
            fma2(ac[0][0], a0, b.x); fma2(ac[0][1], a0, b.y);
            fma2(ac[1][0], a1, b.x); fma2(ac[1][1], a1, b.y);
            fma2(ac[2][0], a2, b.x); fma2(ac[2][1], a2, b.y);
            fma2(ac[3][0], a3, b.x); fma2(ac[3][1], a3, b.y);
        }
        __syncthreads();
    }

    #pragma unroll
    for (int m = 0; m < 4; m++) {
        int rr = r0 + ty4 + m;
        if (rr >= n) continue;
        int ep = base + rr;
        int tok  = g_etok[ep];
        int slot = g_eslot[ep];
        float w  = g_ew[ep];
        float2 c0 = unpack2(ac[m][0]);
        float2 c1 = unpack2(ac[m][1]);
        float4 ov;
        ov.x = c0.x * w; ov.y = c0.y * w; ov.z = c1.x * w; ov.w = c1.y * w;
        *reinterpret_cast<float4*>(
            g_contrib + ((size_t)tok * SLOTS + slot) * H_ + colbase + tx4) = ov;
    }
}

// ---------------- kernel 7: deterministic 10-slot reduce ----------------
__global__ void k_reduce(float* __restrict__ out) {
    int idx = blockIdx.x * 256 + threadIdx.x;   // t*H + h
    int t = idx >> 10;
    int h = idx & 1023;
    const float* c = g_contrib + (size_t)t * SLOTS * H_ + h;
    float s = 0.f;
    #pragma unroll
    for (int j = 0; j < SLOTS; j++) s += c[(size_t)j * H_];
    out[idx] = s;
}

// ---------------- launch ----------------
extern "C" void kernel_launch(void* const* d_in, const int* in_sizes, int n_in,
                              void* d_out, int out_size) {
    const float* x      = (const float*)d_in[0];   // [T,H]
    const float* gate_w = (const float*)d_in[1];   // [E,H]
    const float* w_gu   = (const float*)d_in[2];   // [E,H,2I]
    const float* w_d    = (const float*)d_in[3];   // [E,I,H]
    const float* s_gu   = (const float*)d_in[4];   // [S,H,2I]
    const float* s_d    = (const float*)d_in[5];   // [S,I,H]
    float* out = (float*)d_out;                    // [T,H]

    k_init<<<1, 64>>>();
    k_gate<<<T_ / 16, 256>>>(x, gate_w);
    k_topk<<<T_ / 256, 256>>>();
    k_off<<<1, 32>>>();
    k_scatter<<<T_ / 256, 256>>>();
    k_gateup<<<dim3(NEXP * MAXTILES, I_ / 128), 256>>>(x, w_gu, s_gu);
    k_down<<<dim3(NEXP * MAXTILES, H_ / 128), 256>>>(w_d, s_d);
    k_reduce<<<(T_ * H_) / 256, 256>>>(out);
}

// round 4
// speedup vs baseline: 1.0006x; 1.0006x over previous
#include <cuda_runtime.h>
#include <math.h>
#include <stdint.h>

// ---------------- problem constants ----------------
#define T_ 1024
#define H_ 1024
#define I_ 512
#define E_ 64
#define S_ 2
#define G_ 8
#define TG_ 4
#define K_ 8
#define NEXP 66                     // 64 routed + 2 shared
#define ROUTED_ENTRIES (T_ * K_)    // 8192
#define ENTRIES (ROUTED_ENTRIES + S_ * T_)  // 10240
#define SLOTS (K_ + S_)             // 10
#define MAXTILES 32                 // ceil(T_/BM), worst case one expert gets all tokens
#define BM 32
#define BK 16

// ---------------- device scratch (static, no allocs) ----------------
__device__ float g_logits[T_ * E_];
__device__ int   g_topk_idx[T_ * K_];
__device__ float g_topk_w[T_ * K_];
__device__ int   g_cnt[NEXP];
__device__ int   g_off[NEXP];
__device__ int   g_fill[E_];
__device__ int   g_etok[ENTRIES];
__device__ int   g_eslot[ENTRIES];
__device__ float g_ew[ENTRIES];
__device__ float g_hidden[(size_t)ENTRIES * I_];        // 21 MB
__device__ float g_contrib[(size_t)T_ * SLOTS * H_];    // 42 MB

// ---------------- packed f32x2 helpers ----------------
typedef unsigned long long u64;

__device__ __forceinline__ u64 pack2(float a, float b) {
    u64 r;
    asm("mov.b64 %0, {%1,%2};" : "=l"(r) : "f"(a), "f"(b));
    return r;
}
__device__ __forceinline__ void fma2(u64& d, u64 a, u64 b) {
    asm("fma.rn.f32x2 %0, %1, %2, %0;" : "+l"(d) : "l"(a), "l"(b));
}
__device__ __forceinline__ float2 unpack2(u64 v) {
    float2 f;
    asm("mov.b64 {%0,%1}, %2;" : "=f"(f.x), "=f"(f.y) : "l"(v));
    return f;
}

// ---------------- kernel 0: zero counters ----------------
__global__ void k_init() {
    int i = threadIdx.x;
    if (i < E_) { g_cnt[i] = 0; g_fill[i] = 0; }
}

// ---------------- kernel 1: gating logits = x @ gate_w^T ----------------
// block: 16 tokens x 64 experts; 256 threads; thread -> 4 tokens, 1 expert
__global__ __launch_bounds__(256) void k_gate(const float* __restrict__ x,
                                              const float* __restrict__ gw) {
    __shared__ float xs[16][64];
    __shared__ float ws[64][65];
    int tid = threadIdx.x;
    int t0 = blockIdx.x * 16;
    int e  = tid & 63;
    int ty = tid >> 6;   // 0..3
    float acc[4] = {0.f, 0.f, 0.f, 0.f};

    for (int k0 = 0; k0 < H_; k0 += 64) {
        #pragma unroll
        for (int j = 0; j < 4; j++) {
            int ii = tid + 256 * j;
            int r = ii >> 6, kk = ii & 63;
            xs[r][kk] = x[(size_t)(t0 + r) * H_ + k0 + kk];
        }
        #pragma unroll
        for (int j = 0; j < 16; j++) {
            int ii = tid + 256 * j;
            int ee = ii >> 6, kk = ii & 63;
            ws[kk][ee] = gw[(size_t)ee * H_ + k0 + kk];
        }
        __syncthreads();
        #pragma unroll 8
        for (int kk = 0; kk < 64; kk++) {
            float b = ws[kk][e];
            #pragma unroll
            for (int m = 0; m < 4; m++) acc[m] += xs[ty + 4 * m][kk] * b;
        }
        __syncthreads();
    }
    #pragma unroll
    for (int m = 0; m < 4; m++)
        g_logits[(size_t)(t0 + ty + 4 * m) * E_ + e] = acc[m];
}

// ---------------- kernel 2: grouped top-k per token ----------------
__global__ void k_topk() {
    int t = blockIdx.x * blockDim.x + threadIdx.x;
    if (t >= T_) return;

    float lv[E_];
    #pragma unroll
    for (int e = 0; e < E_; e++) lv[e] = g_logits[(size_t)t * E_ + e];

    // per-group top-4 (group size = E/G = 8), candidates in (group, rank) order
    float cv[G_ * TG_];
    int   ce[G_ * TG_];   // expert index within group
    #pragma unroll
    for (int g = 0; g < G_; g++) {
        float tmp[8];
        #pragma unroll
        for (int j = 0; j < 8; j++) tmp[j] = lv[g * 8 + j];
        #pragma unroll
        for (int r = 0; r < TG_; r++) {
            int bi = 0; float bv = tmp[0];
            #pragma unroll
            for (int j = 1; j < 8; j++)
                if (tmp[j] > bv) { bv = tmp[j]; bi = j; }
            cv[g * TG_ + r] = bv;
            ce[g * TG_ + r] = bi;
            tmp[bi] = -INFINITY;
        }
    }
    // global top-8 over 32 candidates
    float tw[K_]; int tix[K_];
    float wsum = 0.f;
    #pragma unroll
    for (int r = 0; r < K_; r++) {
        int bi = 0; float bv = cv[0];
        #pragma unroll
        for (int j = 1; j < G_ * TG_; j++)
            if (cv[j] > bv) { bv = cv[j]; bi = j; }
        int grp = bi / TG_;
        tw[r]  = bv;
        tix[r] = grp * 8 + ce[bi];
        cv[bi] = -INFINITY;
        wsum  += bv;
    }
    float inv = 1.0f / (wsum + 1e-20f);
    #pragma unroll
    for (int r = 0; r < K_; r++) {
        g_topk_idx[t * K_ + r] = tix[r];
        g_topk_w[t * K_ + r]   = tw[r] * inv;
        atomicAdd(&g_cnt[tix[r]], 1);
    }
}

// ---------------- kernel 3: offsets (serial scan over 64 counts) ----------------
__global__ void k_off() {
    if (threadIdx.x == 0 && blockIdx.x == 0) {
        int run = 0;
        for (int e = 0; e < E_; e++) { g_off[e] = run; run += g_cnt[e]; }
        g_off[E_]     = ROUTED_ENTRIES;
        g_off[E_ + 1] = ROUTED_ENTRIES + T_;
        g_cnt[E_]     = T_;
        g_cnt[E_ + 1] = T_;
    }
}

// ---------------- kernel 4: scatter entries ----------------
__global__ void k_scatter() {
    int t = blockIdx.x * blockDim.x + threadIdx.x;
    if (t >= T_) return;
    #pragma unroll
    for (int r = 0; r < K_; r++) {
        int e = g_topk_idx[t * K_ + r];
        int p = g_off[e] + atomicAdd(&g_fill[e], 1);
        g_etok[p]  = t;
        g_eslot[p] = r;
        g_ew[p]    = g_topk_w[t * K_ + r];
    }
    #pragma unroll
    for (int s = 0; s < S_; s++) {
        int p = ROUTED_ENTRIES + s * T_ + t;
        g_etok[p]  = t;
        g_eslot[p] = K_ + s;
        g_ew[p]    = 1.0f;
    }
}

// ---------------- kernel 5: gate_up GEMM + fused SiLU ----------------
// grid.x = NEXP*MAXTILES (expert, entry tile of BM), grid.y = I/128 (col tile)
// block 256: thread computes 4 entries x 4 hidden cols, gate+up accumulators.
__global__ __launch_bounds__(256) void k_gateup(const float* __restrict__ x,
                                                const float* __restrict__ w_gu,
                                                const float* __restrict__ s_gu) {
    int e    = blockIdx.x >> 5;    // /MAXTILES
    int tile = blockIdx.x & 31;
    int n = g_cnt[e];
    int r0 = tile * BM;
    if (r0 >= n) return;
    int base = g_off[e];
    int colbase = blockIdx.y * 128;   // within I_
    const float* W = (e < E_) ? (w_gu + (size_t)e * (H_ * 2 * I_))
                              : (s_gu + (size_t)(e - E_) * (H_ * 2 * I_));

    __shared__ __align__(16) float xs[BM][BK];
    __shared__ __align__(16) float wg[BK][128];
    __shared__ __align__(16) float wu[BK][128];

    int tid = threadIdx.x;
    int tx4 = (tid & 31) * 4;   // col within 128-tile
    int ty4 = (tid >> 5) * 4;   // row within BM

    u64 ag[4][2], au[4][2];
    #pragma unroll
    for (int m = 0; m < 4; m++)
        #pragma unroll
        for (int p = 0; p < 2; p++) { ag[m][p] = 0ull; au[m][p] = 0ull; }

    for (int k0 = 0; k0 < H_; k0 += BK) {
        #pragma unroll
        for (int j = 0; j < 2; j++) {
            int i = tid + 256 * j;
            int r = i >> 4, kk = i & 15;
            int rr = r0 + r;
            int tok = (rr < n) ? g_etok[base + rr] : g_etok[base + n - 1];
            xs[r][kk] = x[(size_t)tok * H_ + k0 + kk];
        }
        #pragma unroll
        for (int j = 0; j < 8; j++) {
            int i = tid + 256 * j;
            int kk = i >> 7, c = i & 127;
            size_t rowoff = (size_t)(k0 + kk) * (2 * I_);
            wg[kk][c] = W[rowoff + colbase + c];
            wu[kk][c] = W[rowoff + I_ + colbase + c];
        }
        __syncthreads();
        #pragma unroll
        for (int kk = 0; kk < BK; kk++) {
            float av0 = xs[ty4 + 0][kk];
            float av1 = xs[ty4 + 1][kk];
            float av2 = xs[ty4 + 2][kk];
            float av3 = xs[ty4 + 3][kk];
            u64 a0 = pack2(av0, av0), a1 = pack2(av1, av1);
            u64 a2 = pack2(av2, av2), a3 = pack2(av3, av3);
            ulonglong2 bg = *reinterpret_cast<const ulonglong2*>(&wg[kk][tx4]);
            ulonglong2 bu = *reinterpret_cast<const ulonglong2*>(&wu[kk][tx4]);
            fma2(ag[0][0], a0, bg.x); fma2(ag[0][1], a0, bg.y);
            fma2(ag[1][0], a1, bg.x); fma2(ag[1][1], a1, bg.y);
            fma2(ag[2][0], a2, bg.x); fma2(ag[2][1], a2, bg.y);
            fma2(ag[3][0], a3, bg.x); fma2(ag[3][1], a3, bg.y);
            fma2(au[0][0], a0, bu.x); fma2(au[0][1], a0, bu.y);
            fma2(au[1][0], a1, bu.x); fma2(au[1][1], a1, bu.y);
            fma2(au[2][0], a2, bu.x); fma2(au[2][1], a2, bu.y);
            fma2(au[3][0], a3, bu.x); fma2(au[3][1], a3, bu.y);
        }
        __syncthreads();
    }

    #pragma unroll
    for (int m = 0; m < 4; m++) {
        int rr = r0 + ty4 + m;
        if (rr >= n) continue;
        int ep = base + rr;
        float4 hv;
        float2 g0 = unpack2(ag[m][0]);
        float2 u0 = unpack2(au[m][0]);
        float2 g1 = unpack2(ag[m][1]);
        float2 u1 = unpack2(au[m][1]);
        hv.x = g0.x / (1.0f + expf(-g0.x)) * u0.x;
        hv.y = g0.y / (1.0f + expf(-g0.y)) * u0.y;
        hv.z = g1.x / (1.0f + expf(-g1.x)) * u1.x;
        hv.w = g1.y / (1.0f + expf(-g1.y)) * u1.y;
        *reinterpret_cast<float4*>(g_hidden + (size_t)ep * I_ + colbase + tx4) = hv;
    }
}

// ---------------- kernel 6: down GEMM, weighted, -> contrib[tok][slot][H] ----------------
// grid.x = NEXP*MAXTILES, grid.y = H/128
__global__ __launch_bounds__(256) void k_down(const float* __restrict__ w_d,
                                              const float* __restrict__ s_d) {
    int e    = blockIdx.x >> 5;
    int tile = blockIdx.x & 31;
    int n = g_cnt[e];
    int r0 = tile * BM;
    if (r0 >= n) return;
    int base = g_off[e];
    int colbase = blockIdx.y * 128;   // within H_
    const float* W = (e < E_) ? (w_d + (size_t)e * (I_ * H_))
                              : (s_d + (size_t)(e - E_) * (I_ * H_));

    __shared__ __align__(16) float hs[BM][BK];
    __shared__ __align__(16) float wd[BK][128];

    int tid = threadIdx.x;
    int tx4 = (tid & 31) * 4;
    int ty4 = (tid >> 5) * 4;

    u64 ac[4][2];
    #pragma unroll
    for (int m = 0; m < 4; m++)
        #pragma unroll
        for (int p = 0; p < 2; p++) ac[m][p] = 0ull;

    for (int k0 = 0; k0 < I_; k0 += BK) {
        #pragma unroll
        for (int j = 0; j < 2; j++) {
            int i = tid + 256 * j;
            int r = i >> 4, kk = i & 15;
            int rr = r0 + r;
            int rc = (rr < n) ? rr : (n - 1);
            hs[r][kk] = g_hidden[(size_t)(base + rc) * I_ + k0 + kk];
        }
        #pragma unroll
        for (int j = 0; j < 8; j++) {
            int i = tid + 256 * j;
            int kk = i >> 7, c = i & 127;
            wd[kk][c] = W[(size_t)(k0 + kk) * H_ + colbase + c];
        }
        __syncthreads();
        #pragma unroll
        for (int kk = 0; kk < BK; kk++) {
            float av0 = hs[ty4 + 0][kk];
            float av1 = hs[ty4 + 1][kk];
            float av2 = hs[ty4 + 2][kk];
            float av3 = hs[ty4 + 3][kk];
            u64 a0 = pack2(av0, av0), a1 = pack2(av1, av1);
            u64 a2 = pack2(av2, av2), a3 = pack2(av3, av3);
            ulonglong2 b = *reinterpret_cast<const ulonglong2*>(&wd[kk][tx4]);
            fma2(ac[0][0], a0, b.x); fma2(ac[0][1], a0, b.y);
            fma2(ac[1][0], a1, b.x); fma2(ac[1][1], a1, b.y);
            fma2(ac[2][0], a2, b.x); fma2(ac[2][1], a2, b.y);
            fma2(ac[3][0], a3, b.x); fma2(ac[3][1], a3, b.y);
        }
        __syncthreads();
    }

    #pragma unroll
    for (int m = 0; m < 4; m++) {
        int rr = r0 + ty4 + m;
        if (rr >= n) continue;
        int ep = base + rr;
        int tok  = g_etok[ep];
        int slot = g_eslot[ep];
        float w  = g_ew[ep];
        float2 c0 = unpack2(ac[m][0]);
        float2 c1 = unpack2(ac[m][1]);
        float4 ov;
        ov.x = c0.x * w; ov.y = c0.y * w; ov.z = c1.x * w; ov.w = c1.y * w;
        *reinterpret_cast<float4*>(
            g_contrib + ((size_t)tok * SLOTS + slot) * H_ + colbase + tx4) = ov;
    }
}

// ---------------- kernel 7: deterministic 10-slot reduce ----------------
__global__ void k_reduce(float* __restrict__ out) {
    int idx = blockIdx.x * 256 + threadIdx.x;   // t*H + h
    int t = idx >> 10;
    int h = idx & 1023;
    const float* c = g_contrib + (size_t)t * SLOTS * H_ + h;
    float s = 0.f;
    #pragma unroll
    for (int j = 0; j < SLOTS; j++) s += c[(size_t)j * H_];
    out[idx] = s;
}

// ---------------- launch ----------------
extern "C" void kernel_launch(void* const* d_in, const int* in_sizes, int n_in,
                              void* d_out, int out_size) {
    const float* x      = (const float*)d_in[0];   // [T,H]
    const float* gate_w = (const float*)d_in[1];   // [E,H]
    const float* w_gu   = (const float*)d_in[2];   // [E,H,2I]
    const float* w_d    = (const float*)d_in[3];   // [E,I,H]
    const float* s_gu   = (const float*)d_in[4];   // [S,H,2I]
    const float* s_d    = (const float*)d_in[5];   // [S,I,H]
    float* out = (float*)d_out;                    // [T,H]

    k_init<<<1, 64>>>();
    k_gate<<<T_ / 16, 256>>>(x, gate_w);
    k_topk<<<T_ / 256, 256>>>();
    k_off<<<1, 32>>>();
    k_scatter<<<T_ / 256, 256>>>();
    k_gateup<<<dim3(NEXP * MAXTILES, I_ / 128), 256>>>(x, w_gu, s_gu);
    k_down<<<dim3(NEXP * MAXTILES, H_ / 128), 256>>>(w_d, s_d);
    k_reduce<<<(T_ * H_) / 256, 256>>>(out);
}

// round 6
// speedup vs baseline: 1.5684x; 1.5674x over previous
#include <cuda_runtime.h>
#include <cuda_bf16.h>
#include <math.h>
#include <stdint.h>

#define T_ 1024
#define H_ 1024
#define I_ 512
#define E_ 64
#define S_ 2
#define G_ 8
#define TG_ 4
#define K_ 8
#define NEXP 66
#define ROUTED_ENTRIES (T_ * K_)
#define ENTRIES (ROUTED_ENTRIES + S_ * T_)
#define SLOTS (K_ + S_)
#define MTILES 8

// smem byte offsets (dynamic smem)
#define OFF_RIDX 0              // int[128]
#define OFF_AHI  1024           // 128 x 80B
#define OFF_ALO  (1024 + 10240)
#define OFF_BHI  (1024 + 20480) // 32 x 272B
#define OFF_BLO  (1024 + 20480 + 8704)
#define MM_SMEM  (1024 + 20480 + 17408)

// ---------------- device scratch ----------------
__device__ float g_logits[T_ * E_];
__device__ int   g_topk_idx[T_ * K_];
__device__ float g_topk_w[T_ * K_];
__device__ int   g_cnt[NEXP];
__device__ int   g_off[NEXP];
__device__ int   g_fill[E_];
__device__ int   g_etok[ENTRIES];
__device__ int   g_eslot[ENTRIES];
__device__ float g_ew[ENTRIES];
__device__ __nv_bfloat16 g_x_hi[T_ * H_];
__device__ __nv_bfloat16 g_x_lo[T_ * H_];
__device__ float g_gu[(size_t)ENTRIES * 1024];          // 42 MB
__device__ __nv_bfloat16 g_hid_hi[(size_t)ENTRIES * I_];
__device__ __nv_bfloat16 g_hid_lo[(size_t)ENTRIES * I_];
__device__ float g_contrib[(size_t)T_ * SLOTS * H_];    // 42 MB

// ---------------- helpers ----------------
__device__ __forceinline__ uint32_t smem_u32(const void* p) {
    uint32_t a;
    asm("{ .reg .u64 t; cvta.to.shared.u64 t, %1; cvt.u32.u64 %0, t; }" : "=r"(a) : "l"(p));
    return a;
}
__device__ __forceinline__ void ldmat4(uint32_t r[4], uint32_t addr) {
    asm volatile("ldmatrix.sync.aligned.m8n8.x4.shared.b16 {%0,%1,%2,%3}, [%4];"
        : "=r"(r[0]), "=r"(r[1]), "=r"(r[2]), "=r"(r[3]) : "r"(addr));
}
__device__ __forceinline__ void ldmat2t(uint32_t r[2], uint32_t addr) {
    asm volatile("ldmatrix.sync.aligned.m8n8.x2.trans.shared.b16 {%0,%1}, [%2];"
        : "=r"(r[0]), "=r"(r[1]) : "r"(addr));
}
__device__ __forceinline__ void mma16816(float d[4], const uint32_t a[4], const uint32_t b[2]) {
    asm volatile("mma.sync.aligned.m16n8k16.row.col.f32.bf16.bf16.f32 "
        "{%0,%1,%2,%3}, {%4,%5,%6,%7}, {%8,%9}, {%0,%1,%2,%3};"
        : "+f"(d[0]), "+f"(d[1]), "+f"(d[2]), "+f"(d[3])
        : "r"(a[0]), "r"(a[1]), "r"(a[2]), "r"(a[3]), "r"(b[0]), "r"(b[1]));
}
__device__ __forceinline__ void split2(float f, __nv_bfloat16& h, __nv_bfloat16& l) {
    h = __float2bfloat16_rn(f);
    l = __float2bfloat16_rn(f - __bfloat162float(h));
}
__device__ __forceinline__ uint32_t pkbf(__nv_bfloat16 a, __nv_bfloat16 b) {
    __nv_bfloat162 t; t.x = a; t.y = b;
    return *reinterpret_cast<uint32_t*>(&t);
}
__device__ __forceinline__ void split4(float4 v, uint2& hi, uint2& lo) {
    __nv_bfloat16 h0, h1, h2, h3, l0, l1, l2, l3;
    split2(v.x, h0, l0); split2(v.y, h1, l1);
    split2(v.z, h2, l2); split2(v.w, h3, l3);
    hi = make_uint2(pkbf(h0, h1), pkbf(h2, h3));
    lo = make_uint2(pkbf(l0, l1), pkbf(l2, l3));
}

// ---------------- routing kernels ----------------
__global__ void k_init() {
    int i = threadIdx.x;
    if (i < E_) { g_cnt[i] = 0; g_fill[i] = 0; }
}

__global__ __launch_bounds__(256) void k_splitx(const float* __restrict__ x) {
    int idx = blockIdx.x * 256 + threadIdx.x;
    float4 v = reinterpret_cast<const float4*>(x)[idx];
    uint2 hi, lo;
    split4(v, hi, lo);
    reinterpret_cast<uint2*>(g_x_hi)[idx] = hi;
    reinterpret_cast<uint2*>(g_x_lo)[idx] = lo;
}

__global__ __launch_bounds__(256) void k_gate(const float* __restrict__ x,
                                              const float* __restrict__ gw) {
    __shared__ float xs[16][64];
    __shared__ float ws[64][65];
    int tid = threadIdx.x;
    int t0 = blockIdx.x * 16;
    int e  = tid & 63;
    int ty = tid >> 6;
    float acc[4] = {0.f, 0.f, 0.f, 0.f};
    for (int k0 = 0; k0 < H_; k0 += 64) {
        #pragma unroll
        for (int j = 0; j < 4; j++) {
            int ii = tid + 256 * j;
            int r = ii >> 6, kk = ii & 63;
            xs[r][kk] = x[(size_t)(t0 + r) * H_ + k0 + kk];
        }
        #pragma unroll
        for (int j = 0; j < 16; j++) {
            int ii = tid + 256 * j;
            int ee = ii >> 6, kk = ii & 63;
            ws[kk][ee] = gw[(size_t)ee * H_ + k0 + kk];
        }
        __syncthreads();
        #pragma unroll 8
        for (int kk = 0; kk < 64; kk++) {
            float b = ws[kk][e];
            #pragma unroll
            for (int m = 0; m < 4; m++) acc[m] += xs[ty + 4 * m][kk] * b;
        }
        __syncthreads();
    }
    #pragma unroll
    for (int m = 0; m < 4; m++)
        g_logits[(size_t)(t0 + ty + 4 * m) * E_ + e] = acc[m];
}

__global__ void k_topk() {
    int t = blockIdx.x * blockDim.x + threadIdx.x;
    if (t >= T_) return;
    float lv[E_];
    #pragma unroll
    for (int e = 0; e < E_; e++) lv[e] = g_logits[(size_t)t * E_ + e];
    float cv[G_ * TG_];
    int   ce[G_ * TG_];
    #pragma unroll
    for (int g = 0; g < G_; g++) {
        float tmp[8];
        #pragma unroll
        for (int j = 0; j < 8; j++) tmp[j] = lv[g * 8 + j];
        #pragma unroll
        for (int r = 0; r < TG_; r++) {
            int bi = 0; float bv = tmp[0];
            #pragma unroll
            for (int j = 1; j < 8; j++)
                if (tmp[j] > bv) { bv = tmp[j]; bi = j; }
            cv[g * TG_ + r] = bv;
            ce[g * TG_ + r] = bi;
            tmp[bi] = -INFINITY;
        }
    }
    float tw[K_]; int tix[K_];
    float wsum = 0.f;
    #pragma unroll
    for (int r = 0; r < K_; r++) {
        int bi = 0; float bv = cv[0];
        #pragma unroll
        for (int j = 1; j < G_ * TG_; j++)
            if (cv[j] > bv) { bv = cv[j]; bi = j; }
        int grp = bi / TG_;
        tw[r]  = bv;
        tix[r] = grp * 8 + ce[bi];
        cv[bi] = -INFINITY;
        wsum  += bv;
    }
    float inv = 1.0f / (wsum + 1e-20f);
    #pragma unroll
    for (int r = 0; r < K_; r++) {
        g_topk_idx[t * K_ + r] = tix[r];
        g_topk_w[t * K_ + r]   = tw[r] * inv;
        atomicAdd(&g_cnt[tix[r]], 1);
    }
}

__global__ void k_off() {
    if (threadIdx.x == 0 && blockIdx.x == 0) {
        int run = 0;
        for (int e = 0; e < E_; e++) { g_off[e] = run; run += g_cnt[e]; }
        g_off[E_]     = ROUTED_ENTRIES;
        g_off[E_ + 1] = ROUTED_ENTRIES + T_;
        g_cnt[E_]     = T_;
        g_cnt[E_ + 1] = T_;
    }
}

__global__ void k_scatter() {
    int t = blockIdx.x * blockDim.x + threadIdx.x;
    if (t >= T_) return;
    #pragma unroll
    for (int r = 0; r < K_; r++) {
        int e = g_topk_idx[t * K_ + r];
        int p = g_off[e] + atomicAdd(&g_fill[e], 1);
        g_etok[p]  = t;
        g_eslot[p] = r;
        g_ew[p]    = g_topk_w[t * K_ + r];
    }
    #pragma unroll
    for (int s = 0; s < S_; s++) {
        int p = ROUTED_ENTRIES + s * T_ + t;
        g_etok[p]  = t;
        g_eslot[p] = K_ + s;
        g_ew[p]    = 1.0f;
    }
}

// ---------------- grouped GEMM mainloop (shared by mm1/mm2) ----------------
// A: bf16 hi/lo gmem, rows given by ridx[] with stride AST.
// B: fp32 gmem [k][ldb], cols nb..nb+128; split on the fly.
#define MM_CHUNK(Ahi, Alo, AST, B, ldb, nb, k0)                                   \
    do {                                                                          \
        _Pragma("unroll")                                                         \
        for (int j = 0; j < 2; j++) {                                             \
            int i = tid + 256 * j;                                                \
            int row = i >> 2, seg = i & 3;                                        \
            size_t go = (size_t)ridx[row] * (AST) + (k0) + seg * 8;               \
            uint32_t so = (uint32_t)(row * 80 + seg * 16);                        \
            *reinterpret_cast<uint4*>(smem + OFF_AHI + so) =                      \
                *reinterpret_cast<const uint4*>((Ahi) + go);                      \
            *reinterpret_cast<uint4*>(smem + OFF_ALO + so) =                      \
                *reinterpret_cast<const uint4*>((Alo) + go);                      \
        }                                                                         \
        _Pragma("unroll")                                                         \
        for (int j = 0; j < 4; j++) {                                             \
            int i = tid + 256 * j;                                                \
            int kk = i >> 5, c = i & 31;                                          \
            float4 v = *reinterpret_cast<const float4*>(                          \
                (B) + (size_t)((k0) + kk) * (ldb) + (nb) + c * 4);                \
            uint2 hi, lo;                                                         \
            split4(v, hi, lo);                                                    \
            *reinterpret_cast<uint2*>(smem + OFF_BHI + kk * 272 + c * 8) = hi;    \
            *reinterpret_cast<uint2*>(smem + OFF_BLO + kk * 272 + c * 8) = lo;    \
        }                                                                         \
        __syncthreads();                                                          \
        _Pragma("unroll")                                                         \
        for (int ks = 0; ks < 2; ks++) {                                          \
            uint32_t ah[4][4], al[4][4], bh[4][2], bl[4][2];                      \
            _Pragma("unroll")                                                     \
            for (int mf = 0; mf < 4; mf++) {                                      \
                uint32_t ad = sb + OFF_AHI +                                      \
                    (uint32_t)((wm + mf * 16 + a_r) * 80 + (ks * 16 + a_c) * 2);  \
                ldmat4(ah[mf], ad);                                               \
                ldmat4(al[mf], ad + (OFF_ALO - OFF_AHI));                         \
            }                                                                     \
            _Pragma("unroll")                                                     \
            for (int nf = 0; nf < 4; nf++) {                                      \
                uint32_t bd = sb + OFF_BHI +                                      \
                    (uint32_t)((ks * 16 + b_r) * 272 + (wn + nf * 8) * 2);        \
                ldmat2t(bh[nf], bd);                                              \
                ldmat2t(bl[nf], bd + (OFF_BLO - OFF_BHI));                        \
            }                                                                     \
            _Pragma("unroll")                                                     \
            for (int mf = 0; mf < 4; mf++)                                        \
                _Pragma("unroll")                                                 \
                for (int nf = 0; nf < 4; nf++) {                                  \
                    mma16816(acc[mf][nf], ah[mf], bh[nf]);                        \
                    mma16816(acc[mf][nf], ah[mf], bl[nf]);                        \
                    mma16816(acc[mf][nf], al[mf], bh[nf]);                        \
                }                                                                 \
        }                                                                         \
        __syncthreads();                                                          \
    } while (0)

// ---------------- GEMM1: gate_up -> g_gu fp32 ----------------
__global__ __launch_bounds__(256, 1) void k_mm1(const float* __restrict__ w_gu,
                                                const float* __restrict__ s_gu) {
    int e    = blockIdx.x >> 3;
    int tile = blockIdx.x & 7;
    int n = g_cnt[e];
    int r0 = tile * 128;
    if (r0 >= n) return;
    int base = g_off[e];
    int nb = blockIdx.y * 128;
    const float* B = (e < E_) ? (w_gu + (size_t)e * (H_ * 2 * I_))
                              : (s_gu + (size_t)(e - E_) * (H_ * 2 * I_));

    extern __shared__ __align__(16) char smem[];
    uint32_t sb = smem_u32(smem);
    int tid = threadIdx.x, wid = tid >> 5, lane = tid & 31;
    int* ridx = reinterpret_cast<int*>(smem + OFF_RIDX);
    if (tid < 128) {
        int rr = r0 + tid;
        ridx[tid] = g_etok[base + ((rr < n) ? rr : (n - 1))];
    }
    __syncthreads();

    int wm = (wid & 1) * 64;
    int wn = (wid >> 1) * 32;
    int a_r = lane & 15, a_c = (lane >> 4) * 8;
    int b_r = (lane & 7) + ((lane >> 3) & 1) * 8;

    float acc[4][4][4];
    #pragma unroll
    for (int mf = 0; mf < 4; mf++)
        #pragma unroll
        for (int nf = 0; nf < 4; nf++)
            #pragma unroll
            for (int v = 0; v < 4; v++) acc[mf][nf][v] = 0.f;

    for (int k0 = 0; k0 < H_; k0 += 32)
        MM_CHUNK(g_x_hi, g_x_lo, H_, B, 2 * I_, nb, k0);

    int nrows = n - r0;
    #pragma unroll
    for (int mf = 0; mf < 4; mf++) {
        int rl = wm + mf * 16 + (lane >> 2);
        #pragma unroll
        for (int hf = 0; hf < 2; hf++) {
            int row = rl + hf * 8;
            if (row < nrows) {
                size_t ep = (size_t)(base + r0 + row);
                #pragma unroll
                for (int nf = 0; nf < 4; nf++) {
                    int col = nb + wn + nf * 8 + (lane & 3) * 2;
                    *reinterpret_cast<float2*>(g_gu + ep * 1024 + col) =
                        make_float2(acc[mf][nf][hf * 2], acc[mf][nf][hf * 2 + 1]);
                }
            }
        }
    }
}

// ---------------- SiLU + split -> hidden hi/lo ----------------
__global__ __launch_bounds__(256) void k_silu() {
    int idx = blockIdx.x * 256 + threadIdx.x;    // over ENTRIES * I/4
    int ep = idx >> 7;                           // I/4 = 128
    int c4 = (idx & 127) * 4;
    const float* row = g_gu + (size_t)ep * 1024;
    float4 g = *reinterpret_cast<const float4*>(row + c4);
    float4 u = *reinterpret_cast<const float4*>(row + 512 + c4);
    float4 h;
    h.x = g.x / (1.0f + expf(-g.x)) * u.x;
    h.y = g.y / (1.0f + expf(-g.y)) * u.y;
    h.z = g.z / (1.0f + expf(-g.z)) * u.z;
    h.w = g.w / (1.0f + expf(-g.w)) * u.w;
    uint2 hi, lo;
    split4(h, hi, lo);
    *reinterpret_cast<uint2*>(g_hid_hi + (size_t)ep * I_ + c4) = hi;
    *reinterpret_cast<uint2*>(g_hid_lo + (size_t)ep * I_ + c4) = lo;
}

// ---------------- GEMM2: down, weighted -> contrib ----------------
__global__ __launch_bounds__(256, 1) void k_mm2(const float* __restrict__ w_d,
                                                const float* __restrict__ s_d) {
    int e    = blockIdx.x >> 3;
    int tile = blockIdx.x & 7;
    int n = g_cnt[e];
    int r0 = tile * 128;
    if (r0 >= n) return;
    int base = g_off[e];
    int nb = blockIdx.y * 128;
    const float* B = (e < E_) ? (w_d + (size_t)e * (I_ * H_))
                              : (s_d + (size_t)(e - E_) * (I_ * H_));

    extern __shared__ __align__(16) char smem[];
    uint32_t sb = smem_u32(smem);
    int tid = threadIdx.x, wid = tid >> 5, lane = tid & 31;
    int* ridx = reinterpret_cast<int*>(smem + OFF_RIDX);
    if (tid < 128) {
        int rr = r0 + tid;
        ridx[tid] = base + ((rr < n) ? rr : (n - 1));
    }
    __syncthreads();

    int wm = (wid & 1) * 64;
    int wn = (wid >> 1) * 32;
    int a_r = lane & 15, a_c = (lane >> 4) * 8;
    int b_r = (lane & 7) + ((lane >> 3) & 1) * 8;

    float acc[4][4][4];
    #pragma unroll
    for (int mf = 0; mf < 4; mf++)
        #pragma unroll
        for (int nf = 0; nf < 4; nf++)
            #pragma unroll
            for (int v = 0; v < 4; v++) acc[mf][nf][v] = 0.f;

    for (int k0 = 0; k0 < I_; k0 += 32)
        MM_CHUNK(g_hid_hi, g_hid_lo, I_, B, H_, nb, k0);

    int nrows = n - r0;
    #pragma unroll
    for (int mf = 0; mf < 4; mf++) {
        int rl = wm + mf * 16 + (lane >> 2);
        #pragma unroll
        for (int hf = 0; hf < 2; hf++) {
            int row = rl + hf * 8;
            if (row < nrows) {
                int ep = base + r0 + row;
                int tok  = g_etok[ep];
                int slot = g_eslot[ep];
                float w  = g_ew[ep];
                float* dst = g_contrib + ((size_t)tok * SLOTS + slot) * H_;
                #pragma unroll
                for (int nf = 0; nf < 4; nf++) {
                    int col = nb + wn + nf * 8 + (lane & 3) * 2;
                    *reinterpret_cast<float2*>(dst + col) =
                        make_float2(acc[mf][nf][hf * 2] * w, acc[mf][nf][hf * 2 + 1] * w);
                }
            }
        }
    }
}

// ---------------- deterministic 10-slot reduce ----------------
__global__ void k_reduce(float* __restrict__ out) {
    int idx = blockIdx.x * 256 + threadIdx.x;
    int t = idx >> 10;
    int h = idx & 1023;
    const float* c = g_contrib + (size_t)t * SLOTS * H_ + h;
    float s = 0.f;
    #pragma unroll
    for (int j = 0; j < SLOTS; j++) s += c[(size_t)j * H_];
    out[idx] = s;
}

// ---------------- launch ----------------
extern "C" void kernel_launch(void* const* d_in, const int* in_sizes, int n_in,
                              void* d_out, int out_size) {
    const float* x      = (const float*)d_in[0];
    const float* gate_w = (const float*)d_in[1];
    const float* w_gu   = (const float*)d_in[2];
    const float* w_d    = (const float*)d_in[3];
    const float* s_gu   = (const float*)d_in[4];
    const float* s_d    = (const float*)d_in[5];
    float* out = (float*)d_out;

    cudaFuncSetAttribute(k_mm1, cudaFuncAttributeMaxDynamicSharedMemorySize, MM_SMEM);
    cudaFuncSetAttribute(k_mm2, cudaFuncAttributeMaxDynamicSharedMemorySize, MM_SMEM);

    k_init<<<1, 64>>>();
    k_splitx<<<(T_ * H_) / 1024, 256>>>(x);
    k_gate<<<T_ / 16, 256>>>(x, gate_w);
    k_topk<<<T_ / 256, 256>>>();
    k_off<<<1, 32>>>();
    k_scatter<<<T_ / 256, 256>>>();
    k_mm1<<<dim3(NEXP * MTILES, 8), 256, MM_SMEM>>>(w_gu, s_gu);
    k_silu<<<(ENTRIES * (I_ / 4)) / 256, 256>>>();
    k_mm2<<<dim3(NEXP * MTILES, 8), 256, MM_SMEM>>>(w_d, s_d);
    k_reduce<<<(T_ * H_) / 256, 256>>>(out);
}

// round 7
// speedup vs baseline: 2.1803x; 1.3902x over previous
#include <cuda_runtime.h>
#include <cuda_bf16.h>
#include <math.h>
#include <stdint.h>

#define T_ 1024
#define H_ 1024
#define I_ 512
#define E_ 64
#define S_ 2
#define G_ 8
#define TG_ 4
#define K_ 8
#define NEXP 66
#define ROUTED_ENTRIES (T_ * K_)
#define ENTRIES (ROUTED_ENTRIES + S_ * T_)
#define SLOTS (K_ + S_)

// ---- smem geometry (dynamic) ----
#define A_ST    144                 // bytes per A row (64 bf16 + pad)
#define A_HL    18432               // hi -> lo offset
#define A_STAGE 36864               // per pipeline stage
#define B_ST    272                 // bytes per B k-row (128 bf16 + pad)
#define B_HL    17408
#define B_STAGE 34816
#define OFF_A   1024
#define OFF_B   (1024 + 73728)
#define MM_SMEM (1024 + 73728 + 69632)   // 144384

// ---------------- device scratch ----------------
__device__ float g_logits[T_ * E_];
__device__ int   g_topk_idx[T_ * K_];
__device__ float g_topk_w[T_ * K_];
__device__ int   g_cnt[NEXP];
__device__ int   g_off[NEXP];
__device__ int   g_fill[E_];
__device__ int   g_etok[ENTRIES];
__device__ int   g_eslot[ENTRIES];
__device__ float g_ew[ENTRIES];
__device__ __nv_bfloat16 g_x_hi[T_ * H_];
__device__ __nv_bfloat16 g_x_lo[T_ * H_];
__device__ __nv_bfloat16 g_hid_hi[(size_t)ENTRIES * I_];
__device__ __nv_bfloat16 g_hid_lo[(size_t)ENTRIES * I_];
__device__ float g_contrib[(size_t)T_ * SLOTS * H_];

// ---------------- helpers ----------------
__device__ __forceinline__ uint32_t smem_u32(const void* p) {
    uint32_t a;
    asm("{ .reg .u64 t; cvta.to.shared.u64 t, %1; cvt.u32.u64 %0, t; }" : "=r"(a) : "l"(p));
    return a;
}
__device__ __forceinline__ void ldmat4(uint32_t r[4], uint32_t addr) {
    asm volatile("ldmatrix.sync.aligned.m8n8.x4.shared.b16 {%0,%1,%2,%3}, [%4];"
        : "=r"(r[0]), "=r"(r[1]), "=r"(r[2]), "=r"(r[3]) : "r"(addr));
}
__device__ __forceinline__ void ldmat2t(uint32_t r[2], uint32_t addr) {
    asm volatile("ldmatrix.sync.aligned.m8n8.x2.trans.shared.b16 {%0,%1}, [%2];"
        : "=r"(r[0]), "=r"(r[1]) : "r"(addr));
}
__device__ __forceinline__ void mma16816(float d[4], const uint32_t a[4], const uint32_t b[2]) {
    asm volatile("mma.sync.aligned.m16n8k16.row.col.f32.bf16.bf16.f32 "
        "{%0,%1,%2,%3}, {%4,%5,%6,%7}, {%8,%9}, {%0,%1,%2,%3};"
        : "+f"(d[0]), "+f"(d[1]), "+f"(d[2]), "+f"(d[3])
        : "r"(a[0]), "r"(a[1]), "r"(a[2]), "r"(a[3]), "r"(b[0]), "r"(b[1]));
}
#define CPA16(dst, src) \
    asm volatile("cp.async.cg.shared.global [%0], [%1], 16;" :: "r"(dst), "l"(src))
#define CPA_COMMIT() asm volatile("cp.async.commit_group;" ::: "memory")
#define CPA_WAIT()   asm volatile("cp.async.wait_group 0;" ::: "memory")

__device__ __forceinline__ void split2(float f, __nv_bfloat16& h, __nv_bfloat16& l) {
    h = __float2bfloat16_rn(f);
    l = __float2bfloat16_rn(f - __bfloat162float(h));
}
__device__ __forceinline__ uint32_t pkbf(__nv_bfloat16 a, __nv_bfloat16 b) {
    __nv_bfloat162 t; t.x = a; t.y = b;
    return *reinterpret_cast<uint32_t*>(&t);
}
__device__ __forceinline__ void split4(float4 v, uint2& hi, uint2& lo) {
    __nv_bfloat16 h0, h1, h2, h3, l0, l1, l2, l3;
    split2(v.x, h0, l0); split2(v.y, h1, l1);
    split2(v.z, h2, l2); split2(v.w, h3, l3);
    hi = make_uint2(pkbf(h0, h1), pkbf(h2, h3));
    lo = make_uint2(pkbf(l0, l1), pkbf(l2, l3));
}

// ---------------- routing kernels ----------------
__global__ __launch_bounds__(256) void k_splitx(const float* __restrict__ x) {
    int idx = blockIdx.x * 256 + threadIdx.x;
    float4 v = reinterpret_cast<const float4*>(x)[idx];
    uint2 hi, lo;
    split4(v, hi, lo);
    reinterpret_cast<uint2*>(g_x_hi)[idx] = hi;
    reinterpret_cast<uint2*>(g_x_lo)[idx] = lo;
}

__global__ __launch_bounds__(256) void k_gate(const float* __restrict__ x,
                                              const float* __restrict__ gw) {
    if (blockIdx.x == 0 && threadIdx.x < E_) {
        g_cnt[threadIdx.x] = 0;
        g_fill[threadIdx.x] = 0;
    }
    __shared__ float xs[16][64];
    __shared__ float ws[64][65];
    int tid = threadIdx.x;
    int t0 = blockIdx.x * 16;
    int e  = tid & 63;
    int ty = tid >> 6;
    float acc[4] = {0.f, 0.f, 0.f, 0.f};
    for (int k0 = 0; k0 < H_; k0 += 64) {
        #pragma unroll
        for (int j = 0; j < 4; j++) {
            int ii = tid + 256 * j;
            int r = ii >> 6, kk = ii & 63;
            xs[r][kk] = x[(size_t)(t0 + r) * H_ + k0 + kk];
        }
        #pragma unroll
        for (int j = 0; j < 16; j++) {
            int ii = tid + 256 * j;
            int ee = ii >> 6, kk = ii & 63;
            ws[kk][ee] = gw[(size_t)ee * H_ + k0 + kk];
        }
        __syncthreads();
        #pragma unroll 8
        for (int kk = 0; kk < 64; kk++) {
            float b = ws[kk][e];
            #pragma unroll
            for (int m = 0; m < 4; m++) acc[m] += xs[ty + 4 * m][kk] * b;
        }
        __syncthreads();
    }
    #pragma unroll
    for (int m = 0; m < 4; m++)
        g_logits[(size_t)(t0 + ty + 4 * m) * E_ + e] = acc[m];
}

__global__ void k_topk() {
    int t = blockIdx.x * blockDim.x + threadIdx.x;
    if (t >= T_) return;
    float lv[E_];
    #pragma unroll
    for (int e = 0; e < E_; e++) lv[e] = g_logits[(size_t)t * E_ + e];
    float cv[G_ * TG_];
    int   ce[G_ * TG_];
    #pragma unroll
    for (int g = 0; g < G_; g++) {
        float tmp[8];
        #pragma unroll
        for (int j = 0; j < 8; j++) tmp[j] = lv[g * 8 + j];
        #pragma unroll
        for (int r = 0; r < TG_; r++) {
            int bi = 0; float bv = tmp[0];
            #pragma unroll
            for (int j = 1; j < 8; j++)
                if (tmp[j] > bv) { bv = tmp[j]; bi = j; }
            cv[g * TG_ + r] = bv;
            ce[g * TG_ + r] = bi;
            tmp[bi] = -INFINITY;
        }
    }
    float tw[K_]; int tix[K_];
    float wsum = 0.f;
    #pragma unroll
    for (int r = 0; r < K_; r++) {
        int bi = 0; float bv = cv[0];
        #pragma unroll
        for (int j = 1; j < G_ * TG_; j++)
            if (cv[j] > bv) { bv = cv[j]; bi = j; }
        int grp = bi / TG_;
        tw[r]  = bv;
        tix[r] = grp * 8 + ce[bi];
        cv[bi] = -INFINITY;
        wsum  += bv;
    }
    float inv = 1.0f / (wsum + 1e-20f);
    #pragma unroll
    for (int r = 0; r < K_; r++) {
        g_topk_idx[t * K_ + r] = tix[r];
        g_topk_w[t * K_ + r]   = tw[r] * inv;
        atomicAdd(&g_cnt[tix[r]], 1);
    }
}

__global__ void k_off() {
    if (threadIdx.x == 0 && blockIdx.x == 0) {
        int run = 0;
        for (int e = 0; e < E_; e++) { g_off[e] = run; run += g_cnt[e]; }
        g_off[E_]     = ROUTED_ENTRIES;
        g_off[E_ + 1] = ROUTED_ENTRIES + T_;
        g_cnt[E_]     = T_;
        g_cnt[E_ + 1] = T_;
    }
}

__global__ void k_scatter() {
    int t = blockIdx.x * blockDim.x + threadIdx.x;
    if (t >= T_) return;
    #pragma unroll
    for (int r = 0; r < K_; r++) {
        int e = g_topk_idx[t * K_ + r];
        int p = g_off[e] + atomicAdd(&g_fill[e], 1);
        g_etok[p]  = t;
        g_eslot[p] = r;
        g_ew[p]    = g_topk_w[t * K_ + r];
    }
    #pragma unroll
    for (int s = 0; s < S_; s++) {
        int p = ROUTED_ENTRIES + s * T_ + t;
        g_etok[p]  = t;
        g_eslot[p] = K_ + s;
        g_ew[p]    = 1.0f;
    }
}

// ---------------- pipelined mainloop pieces ----------------
#define MM_A_ISSUE(Ahi, Alo, AST, s, k0)                                          \
    _Pragma("unroll")                                                             \
    for (int j = 0; j < 4; j++) {                                                 \
        int idx = tid + 256 * j;                                                  \
        int row = idx >> 3, seg = idx & 7;                                        \
        size_t go = (size_t)ridx[row] * (AST) + (k0) + seg * 8;                   \
        uint32_t so = sb + OFF_A + (s) * A_STAGE +                                \
            (uint32_t)(row * A_ST + seg * 16);                                    \
        CPA16(so, (Ahi) + go);                                                    \
        CPA16(so + A_HL, (Alo) + go);                                             \
    }

#define MM_B_STORE(s)                                                             \
    _Pragma("unroll")                                                             \
    for (int j = 0; j < 8; j++) {                                                 \
        int idx = tid + 256 * j;                                                  \
        int kk = idx >> 5, c4 = (idx & 31) * 4;                                   \
        uint2 hi, lo;                                                             \
        split4(breg[j], hi, lo);                                                  \
        char* bp = smem + OFF_B + (s) * B_STAGE + kk * B_ST + c4 * 2;             \
        *reinterpret_cast<uint2*>(bp) = hi;                                       \
        *reinterpret_cast<uint2*>(bp + B_HL) = lo;                                \
    }

#define MM_COMPUTE(s)                                                             \
    _Pragma("unroll")                                                             \
    for (int ks = 0; ks < 4; ks++) {                                              \
        uint32_t ah[4][4], al[4][4], bh[4][2], bl[4][2];                          \
        _Pragma("unroll")                                                         \
        for (int mf = 0; mf < 4; mf++) {                                          \
            uint32_t ad = sb + OFF_A + (s) * A_STAGE +                            \
                (uint32_t)((wm + mf * 16 + a_r) * A_ST + (ks * 16 + a_c) * 2);    \
            ldmat4(ah[mf], ad);                                                   \
            ldmat4(al[mf], ad + A_HL);                                            \
        }                                                                         \
        _Pragma("unroll")                                                         \
        for (int nf = 0; nf < 4; nf++) {                                          \
            uint32_t bd = sb + OFF_B + (s) * B_STAGE +                            \
                (uint32_t)((ks * 16 + b_r) * B_ST + (wn + nf * 8) * 2);           \
            ldmat2t(bh[nf], bd);                                                  \
            ldmat2t(bl[nf], bd + B_HL);                                           \
        }                                                                         \
        _Pragma("unroll")                                                         \
        for (int mf = 0; mf < 4; mf++)                                            \
            _Pragma("unroll")                                                     \
            for (int nf = 0; nf < 4; nf++) {                                      \
                mma16816(acc[mf][nf], ah[mf], bh[nf]);                            \
                mma16816(acc[mf][nf], ah[mf], bl[nf]);                            \
                mma16816(acc[mf][nf], al[mf], bh[nf]);                            \
            }                                                                     \
    }

// ---------------- GEMM1: gate_up + fused SiLU -> hidden hi/lo ----------------
// grid (NEXP*8, 8): y selects gate cols [y*64, y*64+64) paired with up cols +512.
__global__ __launch_bounds__(256, 1) void k_mm1(const float* __restrict__ w_gu,
                                                const float* __restrict__ s_gu) {
    int e    = blockIdx.x >> 3;
    int tile = blockIdx.x & 7;
    int n = g_cnt[e];
    int r0 = tile * 128;
    if (r0 >= n) return;
    int base = g_off[e];
    int gb = blockIdx.y * 64;
    const float* B = (e < E_) ? (w_gu + (size_t)e * (H_ * 2 * I_))
                              : (s_gu + (size_t)(e - E_) * (H_ * 2 * I_));

    extern __shared__ __align__(16) char smem[];
    uint32_t sb = smem_u32(smem);
    int tid = threadIdx.x, wid = tid >> 5, lane = tid & 31;
    int* ridx = reinterpret_cast<int*>(smem);
    if (tid < 128) {
        int rr = r0 + tid;
        ridx[tid] = g_etok[base + ((rr < n) ? rr : (n - 1))];
    }
    __syncthreads();

    int wm = (wid & 1) * 64;
    int wn = (wid >> 1) * 32;
    int a_r = lane & 15, a_c = (lane >> 4) * 8;
    int b_r = (lane & 7) + ((lane >> 3) & 1) * 8;

    float acc[4][4][4];
    #pragma unroll
    for (int mf = 0; mf < 4; mf++)
        #pragma unroll
        for (int nf = 0; nf < 4; nf++)
            #pragma unroll
            for (int v = 0; v < 4; v++) acc[mf][nf][v] = 0.f;

    float4 breg[8];
    const int NC = H_ / 64;

    // prologue
    MM_A_ISSUE(g_x_hi, g_x_lo, H_, 0, 0);
    CPA_COMMIT();
    #pragma unroll
    for (int j = 0; j < 8; j++) {
        int idx = tid + 256 * j;
        int kk = idx >> 5, c4 = (idx & 31) * 4;
        int src = (c4 < 64) ? (gb + c4) : (448 + gb + c4);
        breg[j] = *reinterpret_cast<const float4*>(B + (size_t)kk * (2 * I_) + src);
    }
    CPA_WAIT();
    MM_B_STORE(0);
    __syncthreads();

    for (int kc = 0; kc < NC; kc++) {
        int nxt = kc + 1;
        if (nxt < NC) {
            MM_A_ISSUE(g_x_hi, g_x_lo, H_, nxt & 1, nxt * 64);
            CPA_COMMIT();
            #pragma unroll
            for (int j = 0; j < 8; j++) {
                int idx = tid + 256 * j;
                int kk = idx >> 5, c4 = (idx & 31) * 4;
                int src = (c4 < 64) ? (gb + c4) : (448 + gb + c4);
                breg[j] = *reinterpret_cast<const float4*>(
                    B + (size_t)(nxt * 64 + kk) * (2 * I_) + src);
            }
        }
        MM_COMPUTE(kc & 1);
        if (nxt < NC) {
            CPA_WAIT();
            MM_B_STORE(nxt & 1);
        }
        __syncthreads();
    }

    // ---- epilogue: smem transpose, SiLU, split, write hidden ----
    float* otile = reinterpret_cast<float*>(smem + 1024);   // pitch 132 floats
    #pragma unroll
    for (int mf = 0; mf < 4; mf++) {
        #pragma unroll
        for (int hf = 0; hf < 2; hf++) {
            int row = wm + mf * 16 + (lane >> 2) + hf * 8;
            #pragma unroll
            for (int nf = 0; nf < 4; nf++) {
                int col = wn + nf * 8 + (lane & 3) * 2;
                otile[row * 132 + col]     = acc[mf][nf][hf * 2];
                otile[row * 132 + col + 1] = acc[mf][nf][hf * 2 + 1];
            }
        }
    }
    __syncthreads();
    int nrows = n - r0;
    #pragma unroll
    for (int j = 0; j < 8; j++) {
        int idx = tid + 256 * j;        // 2048 = 128 rows x 16 col-groups
        int row = idx >> 4;
        int cg  = (idx & 15) * 4;
        if (row < nrows) {
            float4 g = *reinterpret_cast<const float4*>(otile + row * 132 + cg);
            float4 u = *reinterpret_cast<const float4*>(otile + row * 132 + 64 + cg);
            float4 h;
            h.x = g.x / (1.0f + expf(-g.x)) * u.x;
            h.y = g.y / (1.0f + expf(-g.y)) * u.y;
            h.z = g.z / (1.0f + expf(-g.z)) * u.z;
            h.w = g.w / (1.0f + expf(-g.w)) * u.w;
            uint2 hi, lo;
            split4(h, hi, lo);
            size_t ep = (size_t)(base + r0 + row);
            *reinterpret_cast<uint2*>(g_hid_hi + ep * I_ + gb + cg) = hi;
            *reinterpret_cast<uint2*>(g_hid_lo + ep * I_ + gb + cg) = lo;
        }
    }
}

// ---------------- GEMM2: down, weighted -> contrib ----------------
__global__ __launch_bounds__(256, 1) void k_mm2(const float* __restrict__ w_d,
                                                const float* __restrict__ s_d) {
    int e    = blockIdx.x >> 3;
    int tile = blockIdx.x & 7;
    int n = g_cnt[e];
    int r0 = tile * 128;
    if (r0 >= n) return;
    int base = g_off[e];
    int nb = blockIdx.y * 128;
    const float* B = (e < E_) ? (w_d + (size_t)e * (I_ * H_))
                              : (s_d + (size_t)(e - E_) * (I_ * H_));

    extern __shared__ __align__(16) char smem[];
    uint32_t sb = smem_u32(smem);
    int tid = threadIdx.x, wid = tid >> 5, lane = tid & 31;
    int* ridx = reinterpret_cast<int*>(smem);
    if (tid < 128) {
        int rr = r0 + tid;
        ridx[tid] = base + ((rr < n) ? rr : (n - 1));
    }
    __syncthreads();

    int wm = (wid & 1) * 64;
    int wn = (wid >> 1) * 32;
    int a_r = lane & 15, a_c = (lane >> 4) * 8;
    int b_r = (lane & 7) + ((lane >> 3) & 1) * 8;

    float acc[4][4][4];
    #pragma unroll
    for (int mf = 0; mf < 4; mf++)
        #pragma unroll
        for (int nf = 0; nf < 4; nf++)
            #pragma unroll
            for (int v = 0; v < 4; v++) acc[mf][nf][v] = 0.f;

    float4 breg[8];
    const int NC = I_ / 64;

    MM_A_ISSUE(g_hid_hi, g_hid_lo, I_, 0, 0);
    CPA_COMMIT();
    #pragma unroll
    for (int j = 0; j < 8; j++) {
        int idx = tid + 256 * j;
        int kk = idx >> 5, c4 = (idx & 31) * 4;
        breg[j] = *reinterpret_cast<const float4*>(B + (size_t)kk * H_ + nb + c4);
    }
    CPA_WAIT();
    MM_B_STORE(0);
    __syncthreads();

    for (int kc = 0; kc < NC; kc++) {
        int nxt = kc + 1;
        if (nxt < NC) {
            MM_A_ISSUE(g_hid_hi, g_hid_lo, I_, nxt & 1, nxt * 64);
            CPA_COMMIT();
            #pragma unroll
            for (int j = 0; j < 8; j++) {
                int idx = tid + 256 * j;
                int kk = idx >> 5, c4 = (idx & 31) * 4;
                breg[j] = *reinterpret_cast<const float4*>(
                    B + (size_t)(nxt * 64 + kk) * H_ + nb + c4);
            }
        }
        MM_COMPUTE(kc & 1);
        if (nxt < NC) {
            CPA_WAIT();
            MM_B_STORE(nxt & 1);
        }
        __syncthreads();
    }

    int nrows = n - r0;
    #pragma unroll
    for (int mf = 0; mf < 4; mf++) {
        int rl = wm + mf * 16 + (lane >> 2);
        #pragma unroll
        for (int hf = 0; hf < 2; hf++) {
            int row = rl + hf * 8;
            if (row < nrows) {
                int ep = base + r0 + row;
                int tok  = g_etok[ep];
                int slot = g_eslot[ep];
                float w  = g_ew[ep];
                float* dst = g_contrib + ((size_t)tok * SLOTS + slot) * H_;
                #pragma unroll
                for (int nf = 0; nf < 4; nf++) {
                    int col = nb + wn + nf * 8 + (lane & 3) * 2;
                    *reinterpret_cast<float2*>(dst + col) =
                        make_float2(acc[mf][nf][hf * 2] * w, acc[mf][nf][hf * 2 + 1] * w);
                }
            }
        }
    }
}

// ---------------- deterministic 10-slot reduce ----------------
__global__ void k_reduce(float* __restrict__ out) {
    int idx = blockIdx.x * 256 + threadIdx.x;
    int t = idx >> 10;
    int h = idx & 1023;
    const float* c = g_contrib + (size_t)t * SLOTS * H_ + h;
    float s = 0.f;
    #pragma unroll
    for (int j = 0; j < SLOTS; j++) s += c[(size_t)j * H_];
    out[idx] = s;
}

// ---------------- launch ----------------
extern "C" void kernel_launch(void* const* d_in, const int* in_sizes, int n_in,
                              void* d_out, int out_size) {
    const float* x      = (const float*)d_in[0];
    const float* gate_w = (const float*)d_in[1];
    const float* w_gu   = (const float*)d_in[2];
    const float* w_d    = (const float*)d_in[3];
    const float* s_gu   = (const float*)d_in[4];
    const float* s_d    = (const float*)d_in[5];
    float* out = (float*)d_out;

    cudaFuncSetAttribute(k_mm1, cudaFuncAttributeMaxDynamicSharedMemorySize, MM_SMEM);
    cudaFuncSetAttribute(k_mm2, cudaFuncAttributeMaxDynamicSharedMemorySize, MM_SMEM);

    k_splitx<<<(T_ * H_) / 1024, 256>>>(x);
    k_gate<<<T_ / 16, 256>>>(x, gate_w);
    k_topk<<<16, 64>>>();
    k_off<<<1, 32>>>();
    k_scatter<<<4, 256>>>();
    k_mm1<<<dim3(NEXP * 8, 8), 256, MM_SMEM>>>(w_gu, s_gu);
    k_mm2<<<dim3(NEXP * 8, 8), 256, MM_SMEM>>>(w_d, s_d);
    k_reduce<<<(T_ * H_) / 256, 256>>>(out);
}

// round 8
// speedup vs baseline: 2.7633x; 1.2674x over previous
#include <cuda_runtime.h>
#include <cuda_fp16.h>
#include <math.h>
#include <stdint.h>

#define T_ 1024
#define H_ 1024
#define I_ 512
#define E_ 64
#define S_ 2
#define G_ 8
#define TG_ 4
#define K_ 8
#define NEXP 66
#define ROUTED_ENTRIES (T_ * K_)
#define ENTRIES (ROUTED_ENTRIES + S_ * T_)
#define SLOTS (K_ + S_)

// ---- smem geometry (dynamic) ----
#define A_ST    144                 // bytes per A row (64 fp16 + pad)
#define A_HL    18432               // hi -> lo offset
#define A_STAGE 36864               // per stage (hi+lo)
#define B_ST    272                 // bytes per B k-row (128 fp16 + pad)
#define B_STAGE 17408
#define OFF_A   1024
#define OFF_B   (1024 + 73728)
#define MM_SMEM (1024 + 73728 + 34816)   // 109568

// ---------------- device scratch ----------------
__device__ float g_logits[T_ * E_];
__device__ int   g_topk_idx[T_ * K_];
__device__ float g_topk_w[T_ * K_];
__device__ int   g_cnt[NEXP];
__device__ int   g_off[NEXP];
__device__ int   g_etok[ENTRIES];
__device__ int   g_eslot[ENTRIES];
__device__ float g_ew[ENTRIES];
__device__ __half g_x_hi[T_ * H_];
__device__ __half g_x_lo[T_ * H_];
__device__ __half g_hid_hi[(size_t)ENTRIES * I_];
__device__ __half g_hid_lo[(size_t)ENTRIES * I_];
__device__ float g_contrib[(size_t)T_ * SLOTS * H_];

// ---------------- helpers ----------------
__device__ __forceinline__ uint32_t smem_u32(const void* p) {
    uint32_t a;
    asm("{ .reg .u64 t; cvta.to.shared.u64 t, %1; cvt.u32.u64 %0, t; }" : "=r"(a) : "l"(p));
    return a;
}
__device__ __forceinline__ void ldmat4(uint32_t r[4], uint32_t addr) {
    asm volatile("ldmatrix.sync.aligned.m8n8.x4.shared.b16 {%0,%1,%2,%3}, [%4];"
        : "=r"(r[0]), "=r"(r[1]), "=r"(r[2]), "=r"(r[3]) : "r"(addr));
}
__device__ __forceinline__ void ldmat2t(uint32_t r[2], uint32_t addr) {
    asm volatile("ldmatrix.sync.aligned.m8n8.x2.trans.shared.b16 {%0,%1}, [%2];"
        : "=r"(r[0]), "=r"(r[1]) : "r"(addr));
}
__device__ __forceinline__ void mma16816(float d[4], const uint32_t a[4], const uint32_t b[2]) {
    asm volatile("mma.sync.aligned.m16n8k16.row.col.f32.f16.f16.f32 "
        "{%0,%1,%2,%3}, {%4,%5,%6,%7}, {%8,%9}, {%0,%1,%2,%3};"
        : "+f"(d[0]), "+f"(d[1]), "+f"(d[2]), "+f"(d[3])
        : "r"(a[0]), "r"(a[1]), "r"(a[2]), "r"(a[3]), "r"(b[0]), "r"(b[1]));
}
#define CPA16(dst, src) \
    asm volatile("cp.async.cg.shared.global [%0], [%1], 16;" :: "r"(dst), "l"(src))
#define CPA_COMMIT() asm volatile("cp.async.commit_group;" ::: "memory")
#define CPA_WAIT()   asm volatile("cp.async.wait_group 0;" ::: "memory")

__device__ __forceinline__ uint32_t pkh(__half a, __half b) {
    __half2 t; t.x = a; t.y = b;
    return *reinterpret_cast<uint32_t*>(&t);
}
// split float4 -> fp16 hi + fp16 lo
__device__ __forceinline__ void splitA4(float4 v, uint2& hi, uint2& lo) {
    __half h0 = __float2half_rn(v.x), h1 = __float2half_rn(v.y);
    __half h2 = __float2half_rn(v.z), h3 = __float2half_rn(v.w);
    __half l0 = __float2half_rn(v.x - __half2float(h0));
    __half l1 = __float2half_rn(v.y - __half2float(h1));
    __half l2 = __float2half_rn(v.z - __half2float(h2));
    __half l3 = __float2half_rn(v.w - __half2float(h3));
    hi = make_uint2(pkh(h0, h1), pkh(h2, h3));
    lo = make_uint2(pkh(l0, l1), pkh(l2, l3));
}
// round float4 -> fp16x4
__device__ __forceinline__ uint2 cvt4h(float4 v) {
    return make_uint2(pkh(__float2half_rn(v.x), __float2half_rn(v.y)),
                      pkh(__float2half_rn(v.z), __float2half_rn(v.w)));
}

// ---------------- routing kernels ----------------
__global__ __launch_bounds__(256) void k_splitx(const float* __restrict__ x) {
    int idx = blockIdx.x * 256 + threadIdx.x;
    float4 v = reinterpret_cast<const float4*>(x)[idx];
    uint2 hi, lo;
    splitA4(v, hi, lo);
    reinterpret_cast<uint2*>(g_x_hi)[idx] = hi;
    reinterpret_cast<uint2*>(g_x_lo)[idx] = lo;
}

__global__ __launch_bounds__(256) void k_gate(const float* __restrict__ x,
                                              const float* __restrict__ gw) {
    if (blockIdx.x == 0 && threadIdx.x < E_) g_cnt[threadIdx.x] = 0;
    __shared__ float xs[16][64];
    __shared__ float ws[64][65];
    int tid = threadIdx.x;
    int t0 = blockIdx.x * 16;
    int e  = tid & 63;
    int ty = tid >> 6;
    float acc[4] = {0.f, 0.f, 0.f, 0.f};
    for (int k0 = 0; k0 < H_; k0 += 64) {
        #pragma unroll
        for (int j = 0; j < 4; j++) {
            int ii = tid + 256 * j;
            int r = ii >> 6, kk = ii & 63;
            xs[r][kk] = x[(size_t)(t0 + r) * H_ + k0 + kk];
        }
        #pragma unroll
        for (int j = 0; j < 16; j++) {
            int ii = tid + 256 * j;
            int ee = ii >> 6, kk = ii & 63;
            ws[kk][ee] = gw[(size_t)ee * H_ + k0 + kk];
        }
        __syncthreads();
        #pragma unroll 8
        for (int kk = 0; kk < 64; kk++) {
            float b = ws[kk][e];
            #pragma unroll
            for (int m = 0; m < 4; m++) acc[m] += xs[ty + 4 * m][kk] * b;
        }
        __syncthreads();
    }
    #pragma unroll
    for (int m = 0; m < 4; m++)
        g_logits[(size_t)(t0 + ty + 4 * m) * E_ + e] = acc[m];
}

__global__ void k_topk() {
    int t = blockIdx.x * blockDim.x + threadIdx.x;
    if (t >= T_) return;
    float lv[E_];
    #pragma unroll
    for (int e = 0; e < E_; e++) lv[e] = g_logits[(size_t)t * E_ + e];
    float cv[G_ * TG_];
    int   ce[G_ * TG_];
    #pragma unroll
    for (int g = 0; g < G_; g++) {
        float tmp[8];
        #pragma unroll
        for (int j = 0; j < 8; j++) tmp[j] = lv[g * 8 + j];
        #pragma unroll
        for (int r = 0; r < TG_; r++) {
            int bi = 0; float bv = tmp[0];
            #pragma unroll
            for (int j = 1; j < 8; j++)
                if (tmp[j] > bv) { bv = tmp[j]; bi = j; }
            cv[g * TG_ + r] = bv;
            ce[g * TG_ + r] = bi;
            tmp[bi] = -INFINITY;
        }
    }
    float tw[K_]; int tix[K_];
    float wsum = 0.f;
    #pragma unroll
    for (int r = 0; r < K_; r++) {
        int bi = 0; float bv = cv[0];
        #pragma unroll
        for (int j = 1; j < G_ * TG_; j++)
            if (cv[j] > bv) { bv = cv[j]; bi = j; }
        int grp = bi / TG_;
        tw[r]  = bv;
        tix[r] = grp * 8 + ce[bi];
        cv[bi] = -INFINITY;
        wsum  += bv;
    }
    float inv = 1.0f / (wsum + 1e-20f);
    #pragma unroll
    for (int r = 0; r < K_; r++) {
        g_topk_idx[t * K_ + r] = tix[r];
        g_topk_w[t * K_ + r]   = tw[r] * inv;
        atomicAdd(&g_cnt[tix[r]], 1);
    }
}

// fused scan + scatter: one block, 1024 threads (= T_ tokens)
__global__ __launch_bounds__(1024) void k_scatter() {
    __shared__ int soff[NEXP];
    __shared__ int sfill[E_];
    int tid = threadIdx.x;
    if (tid < E_) sfill[tid] = 0;
    __syncthreads();
    if (tid == 0) {
        int run = 0;
        #pragma unroll
        for (int e = 0; e < E_; e++) { soff[e] = run; run += g_cnt[e]; }
        soff[E_]     = ROUTED_ENTRIES;
        soff[E_ + 1] = ROUTED_ENTRIES + T_;
        g_cnt[E_]     = T_;
        g_cnt[E_ + 1] = T_;
    }
    __syncthreads();
    if (tid < NEXP) g_off[tid] = soff[tid];

    int t = tid;
    #pragma unroll
    for (int r = 0; r < K_; r++) {
        int e = g_topk_idx[t * K_ + r];
        int p = soff[e] + atomicAdd(&sfill[e], 1);
        g_etok[p]  = t;
        g_eslot[p] = r;
        g_ew[p]    = g_topk_w[t * K_ + r];
    }
    #pragma unroll
    for (int s = 0; s < S_; s++) {
        int p = ROUTED_ENTRIES + s * T_ + t;
        g_etok[p]  = t;
        g_eslot[p] = K_ + s;
        g_ew[p]    = 1.0f;
    }
}

// ---------------- pipelined mainloop pieces ----------------
#define MM_A_ISSUE(Ahi, Alo, AST, s, k0)                                          \
    _Pragma("unroll")                                                             \
    for (int j = 0; j < 4; j++) {                                                 \
        int idx = tid + 256 * j;                                                  \
        int row = idx >> 3, seg = idx & 7;                                        \
        size_t go = (size_t)ridx[row] * (AST) + (k0) + seg * 8;                   \
        uint32_t so = sb + OFF_A + (s) * A_STAGE +                                \
            (uint32_t)(row * A_ST + seg * 16);                                    \
        CPA16(so, (Ahi) + go);                                                    \
        CPA16(so + A_HL, (Alo) + go);                                             \
    }

#define MM_B_STORE(s)                                                             \
    _Pragma("unroll")                                                             \
    for (int j = 0; j < 8; j++) {                                                 \
        int idx = tid + 256 * j;                                                  \
        int kk = idx >> 5, c4 = (idx & 31) * 4;                                   \
        char* bp = smem + OFF_B + (s) * B_STAGE + kk * B_ST + c4 * 2;             \
        *reinterpret_cast<uint2*>(bp) = cvt4h(breg[j]);                           \
    }

#define MM_COMPUTE(s)                                                             \
    _Pragma("unroll")                                                             \
    for (int ks = 0; ks < 4; ks++) {                                              \
        uint32_t ah[4][4], al[4][4], bb[4][2];                                    \
        _Pragma("unroll")                                                         \
        for (int mf = 0; mf < 4; mf++) {                                          \
            uint32_t ad = sb + OFF_A + (s) * A_STAGE +                            \
                (uint32_t)((wm + mf * 16 + a_r) * A_ST + (ks * 16 + a_c) * 2);    \
            ldmat4(ah[mf], ad);                                                   \
            ldmat4(al[mf], ad + A_HL);                                            \
        }                                                                         \
        _Pragma("unroll")                                                         \
        for (int nf = 0; nf < 4; nf++) {                                          \
            uint32_t bd = sb + OFF_B + (s) * B_STAGE +                            \
                (uint32_t)((ks * 16 + b_r) * B_ST + (wn + nf * 8) * 2);           \
            ldmat2t(bb[nf], bd);                                                  \
        }                                                                         \
        _Pragma("unroll")                                                         \
        for (int mf = 0; mf < 4; mf++)                                            \
            _Pragma("unroll")                                                     \
            for (int nf = 0; nf < 4; nf++) {                                      \
                mma16816(acc[mf][nf], ah[mf], bb[nf]);                            \
                mma16816(acc[mf][nf], al[mf], bb[nf]);                            \
            }                                                                     \
    }

// ---------------- GEMM1: gate_up + fused SiLU -> hidden hi/lo ----------------
__global__ __launch_bounds__(256, 1) void k_mm1(const float* __restrict__ w_gu,
                                                const float* __restrict__ s_gu) {
    int e    = blockIdx.x >> 3;
    int tile = blockIdx.x & 7;
    int n = g_cnt[e];
    int r0 = tile * 128;
    if (r0 >= n) return;
    int base = g_off[e];
    int gb = blockIdx.y * 64;
    const float* B = (e < E_) ? (w_gu + (size_t)e * (H_ * 2 * I_))
                              : (s_gu + (size_t)(e - E_) * (H_ * 2 * I_));

    extern __shared__ __align__(16) char smem[];
    uint32_t sb = smem_u32(smem);
    int tid = threadIdx.x, wid = tid >> 5, lane = tid & 31;
    int* ridx = reinterpret_cast<int*>(smem);
    if (tid < 128) {
        int rr = r0 + tid;
        ridx[tid] = g_etok[base + ((rr < n) ? rr : (n - 1))];
    }
    __syncthreads();

    int wm = (wid & 1) * 64;
    int wn = (wid >> 1) * 32;
    int a_r = lane & 15, a_c = (lane >> 4) * 8;
    int b_r = (lane & 7) + ((lane >> 3) & 1) * 8;

    float acc[4][4][4];
    #pragma unroll
    for (int mf = 0; mf < 4; mf++)
        #pragma unroll
        for (int nf = 0; nf < 4; nf++)
            #pragma unroll
            for (int v = 0; v < 4; v++) acc[mf][nf][v] = 0.f;

    float4 breg[8];
    const int NC = H_ / 64;

    MM_A_ISSUE(g_x_hi, g_x_lo, H_, 0, 0);
    CPA_COMMIT();
    #pragma unroll
    for (int j = 0; j < 8; j++) {
        int idx = tid + 256 * j;
        int kk = idx >> 5, c4 = (idx & 31) * 4;
        int src = (c4 < 64) ? (gb + c4) : (448 + gb + c4);
        breg[j] = *reinterpret_cast<const float4*>(B + (size_t)kk * (2 * I_) + src);
    }
    CPA_WAIT();
    MM_B_STORE(0);
    __syncthreads();

    for (int kc = 0; kc < NC; kc++) {
        int nxt = kc + 1;
        if (nxt < NC) {
            MM_A_ISSUE(g_x_hi, g_x_lo, H_, nxt & 1, nxt * 64);
            CPA_COMMIT();
            #pragma unroll
            for (int j = 0; j < 8; j++) {
                int idx = tid + 256 * j;
                int kk = idx >> 5, c4 = (idx & 31) * 4;
                int src = (c4 < 64) ? (gb + c4) : (448 + gb + c4);
                breg[j] = *reinterpret_cast<const float4*>(
                    B + (size_t)(nxt * 64 + kk) * (2 * I_) + src);
            }
        }
        MM_COMPUTE(kc & 1);
        if (nxt < NC) {
            CPA_WAIT();
            MM_B_STORE(nxt & 1);
        }
        __syncthreads();
    }

    // epilogue: smem transpose, SiLU, split fp16, write hidden
    float* otile = reinterpret_cast<float*>(smem + 1024);   // pitch 132 floats
    #pragma unroll
    for (int mf = 0; mf < 4; mf++) {
        #pragma unroll
        for (int hf = 0; hf < 2; hf++) {
            int row = wm + mf * 16 + (lane >> 2) + hf * 8;
            #pragma unroll
            for (int nf = 0; nf < 4; nf++) {
                int col = wn + nf * 8 + (lane & 3) * 2;
                otile[row * 132 + col]     = acc[mf][nf][hf * 2];
                otile[row * 132 + col + 1] = acc[mf][nf][hf * 2 + 1];
            }
        }
    }
    __syncthreads();
    int nrows = n - r0;
    #pragma unroll
    for (int j = 0; j < 8; j++) {
        int idx = tid + 256 * j;
        int row = idx >> 4;
        int cg  = (idx & 15) * 4;
        if (row < nrows) {
            float4 g = *reinterpret_cast<const float4*>(otile + row * 132 + cg);
            float4 u = *reinterpret_cast<const float4*>(otile + row * 132 + 64 + cg);
            float4 h;
            h.x = g.x / (1.0f + expf(-g.x)) * u.x;
            h.y = g.y / (1.0f + expf(-g.y)) * u.y;
            h.z = g.z / (1.0f + expf(-g.z)) * u.z;
            h.w = g.w / (1.0f + expf(-g.w)) * u.w;
            uint2 hi, lo;
            splitA4(h, hi, lo);
            size_t ep = (size_t)(base + r0 + row);
            *reinterpret_cast<uint2*>(g_hid_hi + ep * I_ + gb + cg) = hi;
            *reinterpret_cast<uint2*>(g_hid_lo + ep * I_ + gb + cg) = lo;
        }
    }
}

// ---------------- GEMM2: down, weighted -> contrib ----------------
__global__ __launch_bounds__(256, 1) void k_mm2(const float* __restrict__ w_d,
                                                const float* __restrict__ s_d) {
    int e    = blockIdx.x >> 3;
    int tile = blockIdx.x & 7;
    int n = g_cnt[e];
    int r0 = tile * 128;
    if (r0 >= n) return;
    int base = g_off[e];
    int nb = blockIdx.y * 128;
    const float* B = (e < E_) ? (w_d + (size_t)e * (I_ * H_))
                              : (s_d + (size_t)(e - E_) * (I_ * H_));

    extern __shared__ __align__(16) char smem[];
    uint32_t sb = smem_u32(smem);
    int tid = threadIdx.x, wid = tid >> 5, lane = tid & 31;
    int* ridx = reinterpret_cast<int*>(smem);
    if (tid < 128) {
        int rr = r0 + tid;
        ridx[tid] = base + ((rr < n) ? rr : (n - 1));
    }
    __syncthreads();

    int wm = (wid & 1) * 64;
    int wn = (wid >> 1) * 32;
    int a_r = lane & 15, a_c = (lane >> 4) * 8;
    int b_r = (lane & 7) + ((lane >> 3) & 1) * 8;

    float acc[4][4][4];
    #pragma unroll
    for (int mf = 0; mf < 4; mf++)
        #pragma unroll
        for (int nf = 0; nf < 4; nf++)
            #pragma unroll
            for (int v = 0; v < 4; v++) acc[mf][nf][v] = 0.f;

    float4 breg[8];
    const int NC = I_ / 64;

    MM_A_ISSUE(g_hid_hi, g_hid_lo, I_, 0, 0);
    CPA_COMMIT();
    #pragma unroll
    for (int j = 0; j < 8; j++) {
        int idx = tid + 256 * j;
        int kk = idx >> 5, c4 = (idx & 31) * 4;
        breg[j] = *reinterpret_cast<const float4*>(B + (size_t)kk * H_ + nb + c4);
    }
    CPA_WAIT();
    MM_B_STORE(0);
    __syncthreads();

    for (int kc = 0; kc < NC; kc++) {
        int nxt = kc + 1;
        if (nxt < NC) {
            MM_A_ISSUE(g_hid_hi, g_hid_lo, I_, nxt & 1, nxt * 64);
            CPA_COMMIT();
            #pragma unroll
            for (int j = 0; j < 8; j++) {
                int idx = tid + 256 * j;
                int kk = idx >> 5, c4 = (idx & 31) * 4;
                breg[j] = *reinterpret_cast<const float4*>(
                    B + (size_t)(nxt * 64 + kk) * H_ + nb + c4);
            }
        }
        MM_COMPUTE(kc & 1);
        if (nxt < NC) {
            CPA_WAIT();
            MM_B_STORE(nxt & 1);
        }
        __syncthreads();
    }

    int nrows = n - r0;
    #pragma unroll
    for (int mf = 0; mf < 4; mf++) {
        int rl = wm + mf * 16 + (lane >> 2);
        #pragma unroll
        for (int hf = 0; hf < 2; hf++) {
            int row = rl + hf * 8;
            if (row < nrows) {
                int ep = base + r0 + row;
                int tok  = g_etok[ep];
                int slot = g_eslot[ep];
                float w  = g_ew[ep];
                float* dst = g_contrib + ((size_t)tok * SLOTS + slot) * H_;
                #pragma unroll
                for (int nf = 0; nf < 4; nf++) {
                    int col = nb + wn + nf * 8 + (lane & 3) * 2;
                    *reinterpret_cast<float2*>(dst + col) =
                        make_float2(acc[mf][nf][hf * 2] * w, acc[mf][nf][hf * 2 + 1] * w);
                }
            }
        }
    }
}

// ---------------- deterministic 10-slot reduce ----------------
__global__ void k_reduce(float* __restrict__ out) {
    int idx = blockIdx.x * 256 + threadIdx.x;
    int t = idx >> 10;
    int h = idx & 1023;
    const float* c = g_contrib + (size_t)t * SLOTS * H_ + h;
    float s = 0.f;
    #pragma unroll
    for (int j = 0; j < SLOTS; j++) s += c[(size_t)j * H_];
    out[idx] = s;
}

// ---------------- launch ----------------
extern "C" void kernel_launch(void* const* d_in, const int* in_sizes, int n_in,
                              void* d_out, int out_size) {
    const float* x      = (const float*)d_in[0];
    const float* gate_w = (const float*)d_in[1];
    const float* w_gu   = (const float*)d_in[2];
    const float* w_d    = (const float*)d_in[3];
    const float* s_gu   = (const float*)d_in[4];
    const float* s_d    = (const float*)d_in[5];
    float* out = (float*)d_out;

    cudaFuncSetAttribute(k_mm1, cudaFuncAttributeMaxDynamicSharedMemorySize, MM_SMEM);
    cudaFuncSetAttribute(k_mm2, cudaFuncAttributeMaxDynamicSharedMemorySize, MM_SMEM);

    k_splitx<<<(T_ * H_) / 1024, 256>>>(x);
    k_gate<<<T_ / 16, 256>>>(x, gate_w);
    k_topk<<<16, 64>>>();
    k_scatter<<<1, 1024>>>();
    k_mm1<<<dim3(NEXP * 8, 8), 256, MM_SMEM>>>(w_gu, s_gu);
    k_mm2<<<dim3(NEXP * 8, 8), 256, MM_SMEM>>>(w_d, s_d);
    k_reduce<<<(T_ * H_) / 256, 256>>>(out);
}

// round 9
// speedup vs baseline: 3.4277x; 1.2404x over previous
#include <cuda_runtime.h>
#include <cuda_fp16.h>
#include <math.h>
#include <stdint.h>

#define T_ 1024
#define H_ 1024
#define I_ 512
#define E_ 64
#define S_ 2
#define G_ 8
#define TG_ 4
#define K_ 8
#define NEXP 66
#define ROUTED_ENTRIES (T_ * K_)
#define ENTRIES (ROUTED_ENTRIES + S_ * T_)
#define SLOTS (K_ + S_)

// ---- smem geometry (dynamic) ----
#define A_ST    144                 // bytes per A row (64 fp16 + pad)
#define A_STAGE 18432
#define B_ST    272                 // bytes per B k-row (128 fp16 + pad)
#define B_STAGE 17408
#define OFF_A   1024
#define OFF_B   (1024 + 2 * A_STAGE)
#define MM_SMEM (1024 + 2 * A_STAGE + 2 * B_STAGE)   // 72704

// ---------------- device scratch ----------------
__device__ float g_logits[T_ * E_];
__device__ int   g_topk_idx[T_ * K_];
__device__ float g_topk_w[T_ * K_];
__device__ int   g_cnt[NEXP];
__device__ int   g_off[NEXP];
__device__ int   g_etok[ENTRIES];
__device__ int   g_eslot[ENTRIES];
__device__ float g_ew[ENTRIES];
__device__ __half g_xh[T_ * H_];
__device__ __half g_hid[(size_t)ENTRIES * I_];
__device__ float g_contrib[(size_t)T_ * SLOTS * H_];

// ---------------- helpers ----------------
__device__ __forceinline__ uint32_t smem_u32(const void* p) {
    uint32_t a;
    asm("{ .reg .u64 t; cvta.to.shared.u64 t, %1; cvt.u32.u64 %0, t; }" : "=r"(a) : "l"(p));
    return a;
}
__device__ __forceinline__ void ldmat4(uint32_t r[4], uint32_t addr) {
    asm volatile("ldmatrix.sync.aligned.m8n8.x4.shared.b16 {%0,%1,%2,%3}, [%4];"
        : "=r"(r[0]), "=r"(r[1]), "=r"(r[2]), "=r"(r[3]) : "r"(addr));
}
__device__ __forceinline__ void ldmat2t(uint32_t r[2], uint32_t addr) {
    asm volatile("ldmatrix.sync.aligned.m8n8.x2.trans.shared.b16 {%0,%1}, [%2];"
        : "=r"(r[0]), "=r"(r[1]) : "r"(addr));
}
__device__ __forceinline__ void mma16816(float d[4], const uint32_t a[4], const uint32_t b[2]) {
    asm volatile("mma.sync.aligned.m16n8k16.row.col.f32.f16.f16.f32 "
        "{%0,%1,%2,%3}, {%4,%5,%6,%7}, {%8,%9}, {%0,%1,%2,%3};"
        : "+f"(d[0]), "+f"(d[1]), "+f"(d[2]), "+f"(d[3])
        : "r"(a[0]), "r"(a[1]), "r"(a[2]), "r"(a[3]), "r"(b[0]), "r"(b[1]));
}
#define CPA16(dst, src) \
    asm volatile("cp.async.cg.shared.global [%0], [%1], 16;" :: "r"(dst), "l"(src))
#define CPA_COMMIT() asm volatile("cp.async.commit_group;" ::: "memory")
#define CPA_WAIT()   asm volatile("cp.async.wait_group 0;" ::: "memory")

__device__ __forceinline__ uint32_t pkh(__half a, __half b) {
    __half2 t; t.x = a; t.y = b;
    return *reinterpret_cast<uint32_t*>(&t);
}
__device__ __forceinline__ uint2 cvt4h(float4 v) {
    return make_uint2(pkh(__float2half_rn(v.x), __float2half_rn(v.y)),
                      pkh(__float2half_rn(v.z), __float2half_rn(v.w)));
}

// ---------------- routing kernels ----------------
__global__ __launch_bounds__(256) void k_cvtx(const float* __restrict__ x) {
    int idx = blockIdx.x * 256 + threadIdx.x;
    float4 v = reinterpret_cast<const float4*>(x)[idx];
    reinterpret_cast<uint2*>(g_xh)[idx] = cvt4h(v);
}

__global__ __launch_bounds__(256) void k_gate(const float* __restrict__ x,
                                              const float* __restrict__ gw) {
    if (blockIdx.x == 0 && threadIdx.x < E_) g_cnt[threadIdx.x] = 0;
    __shared__ float xs[16][64];
    __shared__ float ws[64][65];
    int tid = threadIdx.x;
    int t0 = blockIdx.x * 16;
    int e  = tid & 63;
    int ty = tid >> 6;
    float acc[4] = {0.f, 0.f, 0.f, 0.f};
    for (int k0 = 0; k0 < H_; k0 += 64) {
        #pragma unroll
        for (int j = 0; j < 4; j++) {
            int ii = tid + 256 * j;
            int r = ii >> 6, kk = ii & 63;
            xs[r][kk] = x[(size_t)(t0 + r) * H_ + k0 + kk];
        }
        #pragma unroll
        for (int j = 0; j < 16; j++) {
            int ii = tid + 256 * j;
            int ee = ii >> 6, kk = ii & 63;
            ws[kk][ee] = gw[(size_t)ee * H_ + k0 + kk];
        }
        __syncthreads();
        #pragma unroll 8
        for (int kk = 0; kk < 64; kk++) {
            float b = ws[kk][e];
            #pragma unroll
            for (int m = 0; m < 4; m++) acc[m] += xs[ty + 4 * m][kk] * b;
        }
        __syncthreads();
    }
    #pragma unroll
    for (int m = 0; m < 4; m++)
        g_logits[(size_t)(t0 + ty + 4 * m) * E_ + e] = acc[m];
}

__global__ void k_topk() {
    int t = blockIdx.x * blockDim.x + threadIdx.x;
    if (t >= T_) return;
    float lv[E_];
    #pragma unroll
    for (int e = 0; e < E_; e++) lv[e] = g_logits[(size_t)t * E_ + e];
    float cv[G_ * TG_];
    int   ce[G_ * TG_];
    #pragma unroll
    for (int g = 0; g < G_; g++) {
        float tmp[8];
        #pragma unroll
        for (int j = 0; j < 8; j++) tmp[j] = lv[g * 8 + j];
        #pragma unroll
        for (int r = 0; r < TG_; r++) {
            int bi = 0; float bv = tmp[0];
            #pragma unroll
            for (int j = 1; j < 8; j++)
                if (tmp[j] > bv) { bv = tmp[j]; bi = j; }
            cv[g * TG_ + r] = bv;
            ce[g * TG_ + r] = bi;
            tmp[bi] = -INFINITY;
        }
    }
    float tw[K_]; int tix[K_];
    float wsum = 0.f;
    #pragma unroll
    for (int r = 0; r < K_; r++) {
        int bi = 0; float bv = cv[0];
        #pragma unroll
        for (int j = 1; j < G_ * TG_; j++)
            if (cv[j] > bv) { bv = cv[j]; bi = j; }
        int grp = bi / TG_;
        tw[r]  = bv;
        tix[r] = grp * 8 + ce[bi];
        cv[bi] = -INFINITY;
        wsum  += bv;
    }
    float inv = 1.0f / (wsum + 1e-20f);
    #pragma unroll
    for (int r = 0; r < K_; r++) {
        g_topk_idx[t * K_ + r] = tix[r];
        g_topk_w[t * K_ + r]   = tw[r] * inv;
        atomicAdd(&g_cnt[tix[r]], 1);
    }
}

// stable ballot scatter: one block per expert (+2 shared), fully parallel
__global__ __launch_bounds__(256) void k_scatter() {
    int e = blockIdx.x;
    int tid = threadIdx.x;
    int lane = tid & 31, wid = tid >> 5;
    if (e >= E_) {
        int s = e - E_;
        for (int t = tid; t < T_; t += 256) {
            int p = ROUTED_ENTRIES + s * T_ + t;
            g_etok[p]  = t;
            g_eslot[p] = K_ + s;
            g_ew[p]    = 1.0f;
        }
        if (tid == 0) {
            g_off[e] = ROUTED_ENTRIES + s * T_;
            g_cnt[e] = T_;
        }
        return;
    }
    __shared__ int s_off, s_run, s_wcnt[8];
    if (tid < 32) {
        int v = (lane < e) ? g_cnt[lane] : 0;
        int v2 = (32 + lane < e) ? g_cnt[32 + lane] : 0;
        v += v2;
        #pragma unroll
        for (int o = 16; o > 0; o >>= 1) v += __shfl_down_sync(0xffffffff, v, o);
        if (lane == 0) { s_off = v; s_run = 0; }
    }
    __syncthreads();
    int off = s_off;
    if (tid == 0) g_off[e] = off;

    for (int c = 0; c < T_ * K_; c += 256) {
        int i = c + tid;
        bool m = (g_topk_idx[i] == e);
        unsigned bal = __ballot_sync(0xffffffff, m);
        if (lane == 0) s_wcnt[wid] = __popc(bal);
        __syncthreads();
        int wpre = 0;
        #pragma unroll
        for (int w = 0; w < 8; w++) wpre += (w < wid) ? s_wcnt[w] : 0;
        if (m) {
            int p = off + s_run + wpre + __popc(bal & ((1u << lane) - 1));
            g_etok[p]  = i >> 3;
            g_eslot[p] = i & 7;
            g_ew[p]    = g_topk_w[i];
        }
        __syncthreads();
        if (tid == 0) {
            int tot = 0;
            #pragma unroll
            for (int w = 0; w < 8; w++) tot += s_wcnt[w];
            s_run += tot;
        }
        __syncthreads();
    }
}

// ---------------- pipelined mainloop pieces ----------------
#define MM_A_ISSUE(Asrc, AST, s, k0)                                              \
    _Pragma("unroll")                                                             \
    for (int j = 0; j < 4; j++) {                                                 \
        int idx = tid + 256 * j;                                                  \
        int row = idx >> 3, seg = idx & 7;                                        \
        size_t go = (size_t)ridx[row] * (AST) + (k0) + seg * 8;                   \
        uint32_t so = sb + OFF_A + (s) * A_STAGE +                                \
            (uint32_t)(row * A_ST + seg * 16);                                    \
        CPA16(so, (Asrc) + go);                                                   \
    }

#define MM_B_STORE(s)                                                             \
    _Pragma("unroll")                                                             \
    for (int j = 0; j < 8; j++) {                                                 \
        int idx = tid + 256 * j;                                                  \
        int kk = idx >> 5, c4 = (idx & 31) * 4;                                   \
        char* bp = smem + OFF_B + (s) * B_STAGE + kk * B_ST + c4 * 2;             \
        *reinterpret_cast<uint2*>(bp) = cvt4h(breg[j]);                           \
    }

#define MM_COMPUTE(s)                                                             \
    _Pragma("unroll")                                                             \
    for (int ks = 0; ks < 4; ks++) {                                              \
        uint32_t aa[4][4], bb[4][2];                                              \
        _Pragma("unroll")                                                         \
        for (int mf = 0; mf < 4; mf++) {                                          \
            uint32_t ad = sb + OFF_A + (s) * A_STAGE +                            \
                (uint32_t)((wm + mf * 16 + a_r) * A_ST + (ks * 16 + a_c) * 2);    \
            ldmat4(aa[mf], ad);                                                   \
        }                                                                         \
        _Pragma("unroll")                                                         \
        for (int nf = 0; nf < 4; nf++) {                                          \
            uint32_t bd = sb + OFF_B + (s) * B_STAGE +                            \
                (uint32_t)((ks * 16 + b_r) * B_ST + (wn + nf * 8) * 2);           \
            ldmat2t(bb[nf], bd);                                                  \
        }                                                                         \
        _Pragma("unroll")                                                         \
        for (int mf = 0; mf < 4; mf++)                                            \
            _Pragma("unroll")                                                     \
            for (int nf = 0; nf < 4; nf++)                                        \
                mma16816(acc[mf][nf], aa[mf], bb[nf]);                            \
    }

// ---------------- GEMM1: gate_up + fused SiLU -> hidden fp16 ----------------
// 1D grid: bid = ((e*8 + tile)*8 + col); col fastest => A rows shared in L2.
__global__ __launch_bounds__(256, 1) void k_mm1(const float* __restrict__ w_gu,
                                                const float* __restrict__ s_gu) {
    int bid  = blockIdx.x;
    int gb   = (bid & 7) * 64;
    int tile = (bid >> 3) & 7;
    int e    = bid >> 6;
    int n = g_cnt[e];
    int r0 = tile * 128;
    if (r0 >= n) return;
    int base = g_off[e];
    const float* B = (e < E_) ? (w_gu + (size_t)e * (H_ * 2 * I_))
                              : (s_gu + (size_t)(e - E_) * (H_ * 2 * I_));

    extern __shared__ __align__(16) char smem[];
    uint32_t sb = smem_u32(smem);
    int tid = threadIdx.x, wid = tid >> 5, lane = tid & 31;
    int* ridx = reinterpret_cast<int*>(smem);
    if (tid < 128) {
        int rr = r0 + tid;
        ridx[tid] = g_etok[base + ((rr < n) ? rr : (n - 1))];
    }
    __syncthreads();

    int wm = (wid & 1) * 64;
    int wn = (wid >> 1) * 32;
    int a_r = lane & 15, a_c = (lane >> 4) * 8;
    int b_r = (lane & 7) + ((lane >> 3) & 1) * 8;

    float acc[4][4][4];
    #pragma unroll
    for (int mf = 0; mf < 4; mf++)
        #pragma unroll
        for (int nf = 0; nf < 4; nf++)
            #pragma unroll
            for (int v = 0; v < 4; v++) acc[mf][nf][v] = 0.f;

    float4 breg[8];
    const int NC = H_ / 64;

    MM_A_ISSUE(g_xh, H_, 0, 0);
    CPA_COMMIT();
    #pragma unroll
    for (int j = 0; j < 8; j++) {
        int idx = tid + 256 * j;
        int kk = idx >> 5, c4 = (idx & 31) * 4;
        int src = (c4 < 64) ? (gb + c4) : (448 + gb + c4);
        breg[j] = *reinterpret_cast<const float4*>(B + (size_t)kk * (2 * I_) + src);
    }
    CPA_WAIT();
    MM_B_STORE(0);
    __syncthreads();

    for (int kc = 0; kc < NC; kc++) {
        int nxt = kc + 1;
        if (nxt < NC) {
            MM_A_ISSUE(g_xh, H_, nxt & 1, nxt * 64);
            CPA_COMMIT();
            #pragma unroll
            for (int j = 0; j < 8; j++) {
                int idx = tid + 256 * j;
                int kk = idx >> 5, c4 = (idx & 31) * 4;
                int src = (c4 < 64) ? (gb + c4) : (448 + gb + c4);
                breg[j] = *reinterpret_cast<const float4*>(
                    B + (size_t)(nxt * 64 + kk) * (2 * I_) + src);
            }
        }
        MM_COMPUTE(kc & 1);
        if (nxt < NC) {
            CPA_WAIT();
            MM_B_STORE(nxt & 1);
        }
        __syncthreads();
    }

    // epilogue: smem transpose, SiLU, fp16 hidden
    float* otile = reinterpret_cast<float*>(smem + 1024);   // pitch 132 floats
    #pragma unroll
    for (int mf = 0; mf < 4; mf++) {
        #pragma unroll
        for (int hf = 0; hf < 2; hf++) {
            int row = wm + mf * 16 + (lane >> 2) + hf * 8;
            #pragma unroll
            for (int nf = 0; nf < 4; nf++) {
                int col = wn + nf * 8 + (lane & 3) * 2;
                otile[row * 132 + col]     = acc[mf][nf][hf * 2];
                otile[row * 132 + col + 1] = acc[mf][nf][hf * 2 + 1];
            }
        }
    }
    __syncthreads();
    int nrows = n - r0;
    #pragma unroll
    for (int j = 0; j < 8; j++) {
        int idx = tid + 256 * j;
        int row = idx >> 4;
        int cg  = (idx & 15) * 4;
        if (row < nrows) {
            float4 g = *reinterpret_cast<const float4*>(otile + row * 132 + cg);
            float4 u = *reinterpret_cast<const float4*>(otile + row * 132 + 64 + cg);
            float4 h;
            h.x = g.x / (1.0f + expf(-g.x)) * u.x;
            h.y = g.y / (1.0f + expf(-g.y)) * u.y;
            h.z = g.z / (1.0f + expf(-g.z)) * u.z;
            h.w = g.w / (1.0f + expf(-g.w)) * u.w;
            size_t ep = (size_t)(base + r0 + row);
            *reinterpret_cast<uint2*>(g_hid + ep * I_ + gb + cg) = cvt4h(h);
        }
    }
}

// ---------------- GEMM2: down, weighted -> contrib ----------------
__global__ __launch_bounds__(256, 1) void k_mm2(const float* __restrict__ w_d,
                                                const float* __restrict__ s_d) {
    int bid  = blockIdx.x;
    int nb   = (bid & 7) * 128;
    int tile = (bid >> 3) & 7;
    int e    = bid >> 6;
    int n = g_cnt[e];
    int r0 = tile * 128;
    if (r0 >= n) return;
    int base = g_off[e];
    const float* B = (e < E_) ? (w_d + (size_t)e * (I_ * H_))
                              : (s_d + (size_t)(e - E_) * (I_ * H_));

    extern __shared__ __align__(16) char smem[];
    uint32_t sb = smem_u32(smem);
    int tid = threadIdx.x, wid = tid >> 5, lane = tid & 31;
    int* ridx = reinterpret_cast<int*>(smem);
    if (tid < 128) {
        int rr = r0 + tid;
        ridx[tid] = base + ((rr < n) ? rr : (n - 1));
    }
    __syncthreads();

    int wm = (wid & 1) * 64;
    int wn = (wid >> 1) * 32;
    int a_r = lane & 15, a_c = (lane >> 4) * 8;
    int b_r = (lane & 7) + ((lane >> 3) & 1) * 8;

    float acc[4][4][4];
    #pragma unroll
    for (int mf = 0; mf < 4; mf++)
        #pragma unroll
        for (int nf = 0; nf < 4; nf++)
            #pragma unroll
            for (int v = 0; v < 4; v++) acc[mf][nf][v] = 0.f;

    float4 breg[8];
    const int NC = I_ / 64;

    MM_A_ISSUE(g_hid, I_, 0, 0);
    CPA_COMMIT();
    #pragma unroll
    for (int j = 0; j < 8; j++) {
        int idx = tid + 256 * j;
        int kk = idx >> 5, c4 = (idx & 31) * 4;
        breg[j] = *reinterpret_cast<const float4*>(B + (size_t)kk * H_ + nb + c4);
    }
    CPA_WAIT();
    MM_B_STORE(0);
    __syncthreads();

    for (int kc = 0; kc < NC; kc++) {
        int nxt = kc + 1;
        if (nxt < NC) {
            MM_A_ISSUE(g_hid, I_, nxt & 1, nxt * 64);
            CPA_COMMIT();
            #pragma unroll
            for (int j = 0; j < 8; j++) {
                int idx = tid + 256 * j;
                int kk = idx >> 5, c4 = (idx & 31) * 4;
                breg[j] = *reinterpret_cast<const float4*>(
                    B + (size_t)(nxt * 64 + kk) * H_ + nb + c4);
            }
        }
        MM_COMPUTE(kc & 1);
        if (nxt < NC) {
            CPA_WAIT();
            MM_B_STORE(nxt & 1);
        }
        __syncthreads();
    }

    int nrows = n - r0;
    #pragma unroll
    for (int mf = 0; mf < 4; mf++) {
        int rl = wm + mf * 16 + (lane >> 2);
        #pragma unroll
        for (int hf = 0; hf < 2; hf++) {
            int row = rl + hf * 8;
            if (row < nrows) {
                int ep = base + r0 + row;
                int tok  = g_etok[ep];
                int slot = g_eslot[ep];
                float w  = g_ew[ep];
                float* dst = g_contrib + ((size_t)tok * SLOTS + slot) * H_;
                #pragma unroll
                for (int nf = 0; nf < 4; nf++) {
                    int col = nb + wn + nf * 8 + (lane & 3) * 2;
                    *reinterpret_cast<float2*>(dst + col) =
                        make_float2(acc[mf][nf][hf * 2] * w, acc[mf][nf][hf * 2 + 1] * w);
                }
            }
        }
    }
}

// ---------------- deterministic 10-slot reduce ----------------
__global__ void k_reduce(float* __restrict__ out) {
    int idx = blockIdx.x * 256 + threadIdx.x;
    int t = idx >> 10;
    int h = idx & 1023;
    const float* c = g_contrib + (size_t)t * SLOTS * H_ + h;
    float s = 0.f;
    #pragma unroll
    for (int j = 0; j < SLOTS; j++) s += c[(size_t)j * H_];
    out[idx] = s;
}

// ---------------- launch ----------------
extern "C" void kernel_launch(void* const* d_in, const int* in_sizes, int n_in,
                              void* d_out, int out_size) {
    const float* x      = (const float*)d_in[0];
    const float* gate_w = (const float*)d_in[1];
    const float* w_gu   = (const float*)d_in[2];
    const float* w_d    = (const float*)d_in[3];
    const float* s_gu   = (const float*)d_in[4];
    const float* s_d    = (const float*)d_in[5];
    float* out = (float*)d_out;

    cudaFuncSetAttribute(k_mm1, cudaFuncAttributeMaxDynamicSharedMemorySize, MM_SMEM);
    cudaFuncSetAttribute(k_mm2, cudaFuncAttributeMaxDynamicSharedMemorySize, MM_SMEM);

    k_cvtx<<<(T_ * H_) / 1024, 256>>>(x);
    k_gate<<<T_ / 16, 256>>>(x, gate_w);
    k_topk<<<16, 64>>>();
    k_scatter<<<NEXP, 256>>>();
    k_mm1<<<NEXP * 64, 256, MM_SMEM>>>(w_gu, s_gu);
    k_mm2<<<NEXP * 64, 256, MM_SMEM>>>(w_d, s_d);
    k_reduce<<<(T_ * H_) / 256, 256>>>(out);
}

// round 13
// speedup vs baseline: 4.1935x; 1.2234x over previous
#include <cuda_runtime.h>
#include <cuda_fp16.h>
#include <math.h>
#include <stdint.h>

#define T_ 1024
#define H_ 1024
#define I_ 512
#define E_ 64
#define S_ 2
#define G_ 8
#define TG_ 4
#define K_ 8
#define NEXP 66
#define ROUTED_ENTRIES (T_ * K_)
#define ENTRIES (ROUTED_ENTRIES + S_ * T_)
#define SLOTS (K_ + S_)

// ---- smem geometry (dynamic) ----
#define A_ST    144                 // bytes per A row (64 fp16 + pad)
#define A_STAGE 18432
#define B_ST    272                 // bytes per B k-row (128 fp16 + pad)
#define B_STAGE 17408
#define OFF_A   1024
#define OFF_B   (1024 + 2 * A_STAGE)
#define MM_SMEM (1024 + 2 * A_STAGE + 2 * B_STAGE)   // 72704

// ---------------- device scratch ----------------
__device__ float g_logits[T_ * E_];
__device__ int   g_topk_idx[T_ * K_];
__device__ float g_topk_w[T_ * K_];
__device__ int   g_rank[T_ * K_];
__device__ int   g_cnt[NEXP];
__device__ int   g_off[NEXP];
__device__ int   g_etok[ENTRIES];
__device__ int   g_eslot[ENTRIES];
__device__ float g_ew[ENTRIES];
__device__ __half g_xh[T_ * H_];
__device__ __half g_hid[(size_t)ENTRIES * I_];
__device__ float g_contrib[(size_t)T_ * SLOTS * H_];

// ---------------- helpers ----------------
__device__ __forceinline__ uint32_t smem_u32(const void* p) {
    uint32_t a;
    asm("{ .reg .u64 t; cvta.to.shared.u64 t, %1; cvt.u32.u64 %0, t; }" : "=r"(a) : "l"(p));
    return a;
}
__device__ __forceinline__ void ldmat4(uint32_t r[4], uint32_t addr) {
    asm volatile("ldmatrix.sync.aligned.m8n8.x4.shared.b16 {%0,%1,%2,%3}, [%4];"
        : "=r"(r[0]), "=r"(r[1]), "=r"(r[2]), "=r"(r[3]) : "r"(addr));
}
__device__ __forceinline__ void ldmat2t(uint32_t r[2], uint32_t addr) {
    asm volatile("ldmatrix.sync.aligned.m8n8.x2.trans.shared.b16 {%0,%1}, [%2];"
        : "=r"(r[0]), "=r"(r[1]) : "r"(addr));
}
__device__ __forceinline__ void mma16816(float d[4], const uint32_t a[4], const uint32_t b[2]) {
    asm volatile("mma.sync.aligned.m16n8k16.row.col.f32.f16.f16.f32 "
        "{%0,%1,%2,%3}, {%4,%5,%6,%7}, {%8,%9}, {%0,%1,%2,%3};"
        : "+f"(d[0]), "+f"(d[1]), "+f"(d[2]), "+f"(d[3])
        : "r"(a[0]), "r"(a[1]), "r"(a[2]), "r"(a[3]), "r"(b[0]), "r"(b[1]));
}
#define CPA16(dst, src) \
    asm volatile("cp.async.cg.shared.global [%0], [%1], 16;" :: "r"(dst), "l"(src))
#define CPA_COMMIT() asm volatile("cp.async.commit_group;" ::: "memory")
#define CPA_WAIT()   asm volatile("cp.async.wait_group 0;" ::: "memory")

__device__ __forceinline__ uint32_t pkh(__half a, __half b) {
    __half2 t; t.x = a; t.y = b;
    return *reinterpret_cast<uint32_t*>(&t);
}
__device__ __forceinline__ uint2 cvt4h(float4 v) {
    return make_uint2(pkh(__float2half_rn(v.x), __float2half_rn(v.y)),
                      pkh(__float2half_rn(v.z), __float2half_rn(v.w)));
}

// ---------------- routing kernels ----------------
__global__ __launch_bounds__(256) void k_cvtx(const float* __restrict__ x) {
    int idx = blockIdx.x * 256 + threadIdx.x;
    float4 v = reinterpret_cast<const float4*>(x)[idx];
    reinterpret_cast<uint2*>(g_xh)[idx] = cvt4h(v);
}

__global__ __launch_bounds__(256) void k_gate(const float* __restrict__ x,
                                              const float* __restrict__ gw) {
    if (blockIdx.x == 0 && threadIdx.x < E_) g_cnt[threadIdx.x] = 0;
    __shared__ float xs[16][64];
    __shared__ float ws[64][65];
    int tid = threadIdx.x;
    int t0 = blockIdx.x * 16;
    int e  = tid & 63;
    int ty = tid >> 6;
    float acc[4] = {0.f, 0.f, 0.f, 0.f};
    for (int k0 = 0; k0 < H_; k0 += 64) {
        #pragma unroll
        for (int j = 0; j < 4; j++) {
            int ii = tid + 256 * j;
            int r = ii >> 6, kk = ii & 63;
            xs[r][kk] = x[(size_t)(t0 + r) * H_ + k0 + kk];
        }
        #pragma unroll
        for (int j = 0; j < 16; j++) {
            int ii = tid + 256 * j;
            int ee = ii >> 6, kk = ii & 63;
            ws[kk][ee] = gw[(size_t)ee * H_ + k0 + kk];
        }
        __syncthreads();
        #pragma unroll 8
        for (int kk = 0; kk < 64; kk++) {
            float b = ws[kk][e];
            #pragma unroll
            for (int m = 0; m < 4; m++) acc[m] += xs[ty + 4 * m][kk] * b;
        }
        __syncthreads();
    }
    #pragma unroll
    for (int m = 0; m < 4; m++)
        g_logits[(size_t)(t0 + ty + 4 * m) * E_ + e] = acc[m];
}

__global__ void k_topk() {
    int t = blockIdx.x * blockDim.x + threadIdx.x;
    if (t >= T_) return;
    float lv[E_];
    #pragma unroll
    for (int e = 0; e < E_; e++) lv[e] = g_logits[(size_t)t * E_ + e];
    float cv[G_ * TG_];
    int   ce[G_ * TG_];
    #pragma unroll
    for (int g = 0; g < G_; g++) {
        float tmp[8];
        #pragma unroll
        for (int j = 0; j < 8; j++) tmp[j] = lv[g * 8 + j];
        #pragma unroll
        for (int r = 0; r < TG_; r++) {
            int bi = 0; float bv = tmp[0];
            #pragma unroll
            for (int j = 1; j < 8; j++)
                if (tmp[j] > bv) { bv = tmp[j]; bi = j; }
            cv[g * TG_ + r] = bv;
            ce[g * TG_ + r] = bi;
            tmp[bi] = -INFINITY;
        }
    }
    float tw[K_]; int tix[K_];
    float wsum = 0.f;
    #pragma unroll
    for (int r = 0; r < K_; r++) {
        int bi = 0; float bv = cv[0];
        #pragma unroll
        for (int j = 1; j < G_ * TG_; j++)
            if (cv[j] > bv) { bv = cv[j]; bi = j; }
        int grp = bi / TG_;
        tw[r]  = bv;
        tix[r] = grp * 8 + ce[bi];
        cv[bi] = -INFINITY;
        wsum  += bv;
    }
    float inv = 1.0f / (wsum + 1e-20f);
    #pragma unroll
    for (int r = 0; r < K_; r++) {
        g_topk_idx[t * K_ + r] = tix[r];
        g_topk_w[t * K_ + r]   = tw[r] * inv;
        g_rank[t * K_ + r]     = atomicAdd(&g_cnt[tix[r]], 1);
    }
}

// scatter with precomputed ranks: one block, no atomics
__global__ __launch_bounds__(1024) void k_scatter() {
    __shared__ int soff[E_];
    int tid = threadIdx.x;
    if (tid == 0) {
        int run = 0;
        #pragma unroll
        for (int e = 0; e < E_; e++) { soff[e] = run; run += g_cnt[e]; }
    }
    __syncthreads();
    if (tid < E_) g_off[tid] = soff[tid];
    if (tid == E_)     { g_off[E_]     = ROUTED_ENTRIES;      g_cnt[E_]     = T_; }
    if (tid == E_ + 1) { g_off[E_ + 1] = ROUTED_ENTRIES + T_; g_cnt[E_ + 1] = T_; }

    int t = tid;
    #pragma unroll
    for (int r = 0; r < K_; r++) {
        int i = t * K_ + r;
        int e = g_topk_idx[i];
        int p = soff[e] + g_rank[i];
        g_etok[p]  = t;
        g_eslot[p] = r;
        g_ew[p]    = g_topk_w[i];
    }
    #pragma unroll
    for (int s = 0; s < S_; s++) {
        int p = ROUTED_ENTRIES + s * T_ + t;
        g_etok[p]  = t;
        g_eslot[p] = K_ + s;
        g_ew[p]    = 1.0f;
    }
}

// ---------------- pipelined mainloop pieces ----------------
#define MM_A_ISSUE(Asrc, AST, s, k0)                                              \
    _Pragma("unroll")                                                             \
    for (int j = 0; j < 4; j++) {                                                 \
        int idx = tid + 256 * j;                                                  \
        int row = idx >> 3, seg = idx & 7;                                        \
        size_t go = (size_t)ridx[row] * (AST) + (k0) + seg * 8;                   \
        uint32_t so = sb + OFF_A + (s) * A_STAGE +                                \
            (uint32_t)(row * A_ST + seg * 16);                                    \
        CPA16(so, (Asrc) + go);                                                   \
    }

// store 4-float4 half-chunk (half h covers k-rows h*32..h*32+31)
#define MM_B_STORE_HALF(s, h)                                                     \
    _Pragma("unroll")                                                             \
    for (int j = 0; j < 4; j++) {                                                 \
        int idx = tid + 256 * (j + 4 * (h));                                      \
        int kk = idx >> 5, c4 = (idx & 31) * 4;                                   \
        char* bp = smem + OFF_B + (s) * B_STAGE + kk * B_ST + c4 * 2;             \
        *reinterpret_cast<uint2*>(bp) = cvt4h(breg[j]);                           \
    }

#define MM_COMPUTE(s, ks0, ks1)                                                   \
    _Pragma("unroll")                                                             \
    for (int ks = (ks0); ks < (ks1); ks++) {                                      \
        uint32_t aa[4][4], bb[4][2];                                              \
        _Pragma("unroll")                                                         \
        for (int mf = 0; mf < 4; mf++) {                                          \
            uint32_t ad = sb + OFF_A + (s) * A_STAGE +                            \
                (uint32_t)((wm + mf * 16 + a_r) * A_ST + (ks * 16 + a_c) * 2);    \
            ldmat4(aa[mf], ad);                                                   \
        }                                                                         \
        _Pragma("unroll")                                                         \
        for (int nf = 0; nf < 4; nf++) {                                          \
            uint32_t bd = sb + OFF_B + (s) * B_STAGE +                            \
                (uint32_t)((ks * 16 + b_r) * B_ST + (wn + nf * 8) * 2);           \
            ldmat2t(bb[nf], bd);                                                  \
        }                                                                         \
        _Pragma("unroll")                                                         \
        for (int mf = 0; mf < 4; mf++)                                            \
            _Pragma("unroll")                                                     \
            for (int nf = 0; nf < 4; nf++)                                        \
                mma16816(acc[mf][nf], aa[mf], bb[nf]);                            \
    }

// ---------------- GEMM1: gate_up + fused SiLU -> hidden fp16 ----------------
__global__ __launch_bounds__(256, 2) void k_mm1(const float* __restrict__ w_gu,
                                                const float* __restrict__ s_gu) {
    int bid  = blockIdx.x;
    int gb   = (bid & 7) * 64;
    int tile = (bid >> 3) & 7;
    int e    = bid >> 6;
    int n = g_cnt[e];
    int r0 = tile * 128;
    if (r0 >= n) return;
    int base = g_off[e];
    const float* B = (e < E_) ? (w_gu + (size_t)e * (H_ * 2 * I_))
                              : (s_gu + (size_t)(e - E_) * (H_ * 2 * I_));

    extern __shared__ __align__(16) char smem[];
    uint32_t sb = smem_u32(smem);
    int tid = threadIdx.x, wid = tid >> 5, lane = tid & 31;
    int* ridx = reinterpret_cast<int*>(smem);
    if (tid < 128) {
        int rr = r0 + tid;
        ridx[tid] = g_etok[base + ((rr < n) ? rr : (n - 1))];
    }
    __syncthreads();

    int wm = (wid & 1) * 64;
    int wn = (wid >> 1) * 32;
    int a_r = lane & 15, a_c = (lane >> 4) * 8;
    int b_r = (lane & 7) + ((lane >> 3) & 1) * 8;

    float acc[4][4][4];
    #pragma unroll
    for (int mf = 0; mf < 4; mf++)
        #pragma unroll
        for (int nf = 0; nf < 4; nf++)
            #pragma unroll
            for (int v = 0; v < 4; v++) acc[mf][nf][v] = 0.f;

    float4 breg[4];
    const int NC = H_ / 64;

    // prologue: stage 0
    MM_A_ISSUE(g_xh, H_, 0, 0);
    CPA_COMMIT();
    #pragma unroll
    for (int h = 0; h < 2; h++) {
        #pragma unroll
        for (int j = 0; j < 4; j++) {
            int idx = tid + 256 * (j + 4 * h);
            int kk = idx >> 5, c4 = (idx & 31) * 4;
            int src = (c4 < 64) ? (gb + c4) : (448 + gb + c4);
            breg[j] = *reinterpret_cast<const float4*>(B + (size_t)kk * (2 * I_) + src);
        }
        MM_B_STORE_HALF(0, h);
    }
    CPA_WAIT();
    __syncthreads();

    for (int kc = 0; kc < NC; kc++) {
        int nxt = kc + 1;
        int cs = kc & 1, ns = nxt & 1;
        if (nxt < NC) {
            MM_A_ISSUE(g_xh, H_, ns, nxt * 64);
            CPA_COMMIT();
            #pragma unroll
            for (int j = 0; j < 4; j++) {
                int idx = tid + 256 * j;
                int kk = idx >> 5, c4 = (idx & 31) * 4;
                int src = (c4 < 64) ? (gb + c4) : (448 + gb + c4);
                breg[j] = *reinterpret_cast<const float4*>(
                    B + (size_t)(nxt * 64 + kk) * (2 * I_) + src);
            }
        }
        MM_COMPUTE(cs, 0, 2);
        if (nxt < NC) {
            MM_B_STORE_HALF(ns, 0);
            #pragma unroll
            for (int j = 0; j < 4; j++) {
                int idx = tid + 256 * (j + 4);
                int kk = idx >> 5, c4 = (idx & 31) * 4;
                int src = (c4 < 64) ? (gb + c4) : (448 + gb + c4);
                breg[j] = *reinterpret_cast<const float4*>(
                    B + (size_t)(nxt * 64 + kk) * (2 * I_) + src);
            }
        }
        MM_COMPUTE(cs, 2, 4);
        if (nxt < NC) {
            CPA_WAIT();
            MM_B_STORE_HALF(ns, 1);
        }
        __syncthreads();
    }

    // epilogue: smem transpose, SiLU, fp16 hidden
    float* otile = reinterpret_cast<float*>(smem + 1024);   // pitch 132 floats
    #pragma unroll
    for (int mf = 0; mf < 4; mf++) {
        #pragma unroll
        for (int hf = 0; hf < 2; hf++) {
            int row = wm + mf * 16 + (lane >> 2) + hf * 8;
            #pragma unroll
            for (int nf = 0; nf < 4; nf++) {
                int col = wn + nf * 8 + (lane & 3) * 2;
                otile[row * 132 + col]     = acc[mf][nf][hf * 2];
                otile[row * 132 + col + 1] = acc[mf][nf][hf * 2 + 1];
            }
        }
    }
    __syncthreads();
    int nrows = n - r0;
    #pragma unroll
    for (int j = 0; j < 8; j++) {
        int idx = tid + 256 * j;
        int row = idx >> 4;
        int cg  = (idx & 15) * 4;
        if (row < nrows) {
            float4 g = *reinterpret_cast<const float4*>(otile + row * 132 + cg);
            float4 u = *reinterpret_cast<const float4*>(otile + row * 132 + 64 + cg);
            float4 h;
            h.x = g.x / (1.0f + expf(-g.x)) * u.x;
            h.y = g.y / (1.0f + expf(-g.y)) * u.y;
            h.z = g.z / (1.0f + expf(-g.z)) * u.z;
            h.w = g.w / (1.0f + expf(-g.w)) * u.w;
            size_t ep = (size_t)(base + r0 + row);
            *reinterpret_cast<uint2*>(g_hid + ep * I_ + gb + cg) = cvt4h(h);
        }
    }
}

// ---------------- GEMM2: down, weighted -> contrib ----------------
__global__ __launch_bounds__(256, 2) void k_mm2(const float* __restrict__ w_d,
                                                const float* __restrict__ s_d) {
    int bid  = blockIdx.x;
    int nb   = (bid & 7) * 128;
    int tile = (bid >> 3) & 7;
    int e    = bid >> 6;
    int n = g_cnt[e];
    int r0 = tile * 128;
    if (r0 >= n) return;
    int base = g_off[e];
    const float* B = (e < E_) ? (w_d + (size_t)e * (I_ * H_))
                              : (s_d + (size_t)(e - E_) * (I_ * H_));

    extern __shared__ __align__(16) char smem[];
    uint32_t sb = smem_u32(smem);
    int tid = threadIdx.x, wid = tid >> 5, lane = tid & 31;
    int* ridx = reinterpret_cast<int*>(smem);
    if (tid < 128) {
        int rr = r0 + tid;
        ridx[tid] = base + ((rr < n) ? rr : (n - 1));
    }
    __syncthreads();

    int wm = (wid & 1) * 64;
    int wn = (wid >> 1) * 32;
    int a_r = lane & 15, a_c = (lane >> 4) * 8;
    int b_r = (lane & 7) + ((lane >> 3) & 1) * 8;

    float acc[4][4][4];
    #pragma unroll
    for (int mf = 0; mf < 4; mf++)
        #pragma unroll
        for (int nf = 0; nf < 4; nf++)
            #pragma unroll
            for (int v = 0; v < 4; v++) acc[mf][nf][v] = 0.f;

    float4 breg[4];
    const int NC = I_ / 64;

    MM_A_ISSUE(g_hid, I_, 0, 0);
    CPA_COMMIT();
    #pragma unroll
    for (int h = 0; h < 2; h++) {
        #pragma unroll
        for (int j = 0; j < 4; j++) {
            int idx = tid + 256 * (j + 4 * h);
            int kk = idx >> 5, c4 = (idx & 31) * 4;
            breg[j] = *reinterpret_cast<const float4*>(B + (size_t)kk * H_ + nb + c4);
        }
        MM_B_STORE_HALF(0, h);
    }
    CPA_WAIT();
    __syncthreads();

    for (int kc = 0; kc < NC; kc++) {
        int nxt = kc + 1;
        int cs = kc & 1, ns = nxt & 1;
        if (nxt < NC) {
            MM_A_ISSUE(g_hid, I_, ns, nxt * 64);
            CPA_COMMIT();
            #pragma unroll
            for (int j = 0; j < 4; j++) {
                int idx = tid + 256 * j;
                int kk = idx >> 5, c4 = (idx & 31) * 4;
                breg[j] = *reinterpret_cast<const float4*>(
                    B + (size_t)(nxt * 64 + kk) * H_ + nb + c4);
            }
        }
        MM_COMPUTE(cs, 0, 2);
        if (nxt < NC) {
            MM_B_STORE_HALF(ns, 0);
            #pragma unroll
            for (int j = 0; j < 4; j++) {
                int idx = tid + 256 * (j + 4);
                int kk = idx >> 5, c4 = (idx & 31) * 4;
                breg[j] = *reinterpret_cast<const float4*>(
                    B + (size_t)(nxt * 64 + kk) * H_ + nb + c4);
            }
        }
        MM_COMPUTE(cs, 2, 4);
        if (nxt < NC) {
            CPA_WAIT();
            MM_B_STORE_HALF(ns, 1);
        }
        __syncthreads();
    }

    int nrows = n - r0;
    #pragma unroll
    for (int mf = 0; mf < 4; mf++) {
        int rl = wm + mf * 16 + (lane >> 2);
        #pragma unroll
        for (int hf = 0; hf < 2; hf++) {
            int row = rl + hf * 8;
            if (row < nrows) {
                int ep = base + r0 + row;
                int tok  = g_etok[ep];
                int slot = g_eslot[ep];
                float w  = g_ew[ep];
                float* dst = g_contrib + ((size_t)tok * SLOTS + slot) * H_;
                #pragma unroll
                for (int nf = 0; nf < 4; nf++) {
                    int col = nb + wn + nf * 8 + (lane & 3) * 2;
                    *reinterpret_cast<float2*>(dst + col) =
                        make_float2(acc[mf][nf][hf * 2] * w, acc[mf][nf][hf * 2 + 1] * w);
                }
            }
        }
    }
}

// ---------------- deterministic 10-slot reduce ----------------
__global__ void k_reduce(float* __restrict__ out) {
    int idx = blockIdx.x * 256 + threadIdx.x;
    int t = idx >> 10;
    int h = idx & 1023;
    const float* c = g_contrib + (size_t)t * SLOTS * H_ + h;
    float s = 0.f;
    #pragma unroll
    for (int j = 0; j < SLOTS; j++) s += c[(size_t)j * H_];
    out[idx] = s;
}

// ---------------- launch ----------------
extern "C" void kernel_launch(void* const* d_in, const int* in_sizes, int n_in,
                              void* d_out, int out_size) {
    const float* x      = (const float*)d_in[0];
    const float* gate_w = (const float*)d_in[1];
    const float* w_gu   = (const float*)d_in[2];
    const float* w_d    = (const float*)d_in[3];
    const float* s_gu   = (const float*)d_in[4];
    const float* s_d    = (const float*)d_in[5];
    float* out = (float*)d_out;

    cudaFuncSetAttribute(k_mm1, cudaFuncAttributeMaxDynamicSharedMemorySize, MM_SMEM);
    cudaFuncSetAttribute(k_mm2, cudaFuncAttributeMaxDynamicSharedMemorySize, MM_SMEM);

    k_cvtx<<<(T_ * H_) / 1024, 256>>>(x);
    k_gate<<<T_ / 16, 256>>>(x, gate_w);
    k_topk<<<16, 64>>>();
    k_scatter<<<1, 1024>>>();
    k_mm1<<<NEXP * 64, 256, MM_SMEM>>>(w_gu, s_gu);
    k_mm2<<<NEXP * 64, 256, MM_SMEM>>>(w_d, s_d);
    k_reduce<<<(T_ * H_) / 256, 256>>>(out);
}